// round 1
// baseline (speedup 1.0000x reference)
#include <cuda_runtime.h>
#include <math.h>

#define D_MODEL   256
#define NUM_HEADS 8
#define DIM_HEAD  32
#define S_LEN     4096
#define MAX_B     2
#define LN_EPS    1e-6f

// Scratch (allocation-free rule: device globals)
__device__ float g_q[MAX_B * NUM_HEADS * S_LEN * DIM_HEAD];
__device__ float g_k[MAX_B * NUM_HEADS * S_LEN * DIM_HEAD];
__device__ float g_v[MAX_B * NUM_HEADS * S_LEN * DIM_HEAD];
__device__ float g_o[MAX_B * NUM_HEADS * S_LEN * DIM_HEAD];

// ---------------------------------------------------------------------------
// Kernel 1: QKV projection. out = x @ W + b, written as [B,H,S,Dh].
// grid = (N/32, 3), block = 256. Each block: 32 rows x 256 cols of one matrix.
// Thread microtile: 8 rows x 4 cols.
// ---------------------------------------------------------------------------
__global__ void qkv_kernel(const float* __restrict__ x,
                           const float* __restrict__ Wq, const float* __restrict__ bq,
                           const float* __restrict__ Wk, const float* __restrict__ bk,
                           const float* __restrict__ Wv, const float* __restrict__ bv) {
    __shared__ float xs[32][D_MODEL];

    const float* W;
    const float* bias;
    float* out;
    if (blockIdx.y == 0)      { W = Wq; bias = bq; out = g_q; }
    else if (blockIdx.y == 1) { W = Wk; bias = bk; out = g_k; }
    else                      { W = Wv; bias = bv; out = g_v; }

    const int n0  = blockIdx.x * 32;
    const int tid = threadIdx.x;

    // Stage x tile (32x256) into smem, vectorized.
    {
        const float4* xsrc = reinterpret_cast<const float4*>(x + (size_t)n0 * D_MODEL);
        float4* xdst = reinterpret_cast<float4*>(&xs[0][0]);
        #pragma unroll
        for (int i = tid; i < 32 * D_MODEL / 4; i += 256) xdst[i] = xsrc[i];
    }
    __syncthreads();

    const int cg = (tid & 63) * 4;   // column group (4 cols)
    const int rg = (tid >> 6) * 8;   // row group (8 rows)

    float acc[8][4];
    {
        const float4 bb = *reinterpret_cast<const float4*>(&bias[cg]);
        #pragma unroll
        for (int j = 0; j < 8; j++) {
            acc[j][0] = bb.x; acc[j][1] = bb.y; acc[j][2] = bb.z; acc[j][3] = bb.w;
        }
    }

    #pragma unroll 4
    for (int k = 0; k < D_MODEL; k += 4) {
        const float4 w0 = *reinterpret_cast<const float4*>(&W[(k + 0) * D_MODEL + cg]);
        const float4 w1 = *reinterpret_cast<const float4*>(&W[(k + 1) * D_MODEL + cg]);
        const float4 w2 = *reinterpret_cast<const float4*>(&W[(k + 2) * D_MODEL + cg]);
        const float4 w3 = *reinterpret_cast<const float4*>(&W[(k + 3) * D_MODEL + cg]);
        #pragma unroll
        for (int j = 0; j < 8; j++) {
            const float4 xv = *reinterpret_cast<const float4*>(&xs[rg + j][k]);
            acc[j][0] += xv.x * w0.x + xv.y * w1.x + xv.z * w2.x + xv.w * w3.x;
            acc[j][1] += xv.x * w0.y + xv.y * w1.y + xv.z * w2.y + xv.w * w3.y;
            acc[j][2] += xv.x * w0.z + xv.y * w1.z + xv.z * w2.z + xv.w * w3.z;
            acc[j][3] += xv.x * w0.w + xv.y * w1.w + xv.z * w2.w + xv.w * w3.w;
        }
    }

    // Store to [B,H,S,Dh]: col c = h*32+dh; cg%4==0 so 4 cols share a head.
    const int h  = cg >> 5;
    const int dh = cg & 31;
    #pragma unroll
    for (int j = 0; j < 8; j++) {
        const int n = n0 + rg + j;
        const int b = n / S_LEN;
        const int s = n - b * S_LEN;
        float4 v = make_float4(acc[j][0], acc[j][1], acc[j][2], acc[j][3]);
        *reinterpret_cast<float4*>(
            &out[(((size_t)(b * NUM_HEADS + h)) * S_LEN + s) * DIM_HEAD + dh]) = v;
    }
}

// ---------------------------------------------------------------------------
// Kernel 2: flash attention, fp32 SIMT.
// grid = (S/64, H, B), block = 256.
// Score phase: thread (ty=tid/16, tx=tid%16) computes a 4q x 4k microtile.
// PV phase: same thread owns rows ty*4..+3, dims d0=tx*2..+1.
// ---------------------------------------------------------------------------
#define BQ 64
#define BK 64
#define SM_SCALE 0.1767766952966369f  // 1/sqrt(32)

__global__ void attn_kernel(const float* __restrict__ pad_mask) {
    __shared__ float Qs[BQ][36];
    __shared__ float Ks[BK][36];
    __shared__ float Vs[BK][36];
    __shared__ float Ps[BQ][68];
    __shared__ float Ms[BK];

    const int qt = blockIdx.x;
    const int h  = blockIdx.y;
    const int b  = blockIdx.z;
    const int tid = threadIdx.x;

    const size_t head_base = ((size_t)(b * NUM_HEADS + h)) * S_LEN * DIM_HEAD;
    const float* Qp = g_q + head_base + (size_t)qt * BQ * DIM_HEAD;

    // Load Q tile (64x32) once.
    #pragma unroll
    for (int i = tid; i < BQ * 8; i += 256) {
        const int r = i >> 3, c = (i & 7) * 4;
        *reinterpret_cast<float4*>(&Qs[r][c]) =
            *reinterpret_cast<const float4*>(&Qp[r * DIM_HEAD + c]);
    }

    const int ty = tid >> 4;   // 0..15 -> q rows ty*4..+3
    const int tx = tid & 15;   // 0..15 -> keys tx*4..+3 ; dims tx*2..+1
    const int qr0 = ty * 4;
    const int d0 = tx * 2;

    float m[4], l[4], O[4][2];
    #pragma unroll
    for (int i = 0; i < 4; i++) {
        m[i] = -1e30f; l[i] = 0.f; O[i][0] = 0.f; O[i][1] = 0.f;
    }

    for (int kt = 0; kt < S_LEN / BK; kt++) {
        // Load K, V tiles + mask.
        const float* Kp = g_k + head_base + (size_t)kt * BK * DIM_HEAD;
        const float* Vp = g_v + head_base + (size_t)kt * BK * DIM_HEAD;
        #pragma unroll
        for (int i = tid; i < BK * 8; i += 256) {
            const int r = i >> 3, c = (i & 7) * 4;
            *reinterpret_cast<float4*>(&Ks[r][c]) =
                *reinterpret_cast<const float4*>(&Kp[r * DIM_HEAD + c]);
            *reinterpret_cast<float4*>(&Vs[r][c]) =
                *reinterpret_cast<const float4*>(&Vp[r * DIM_HEAD + c]);
        }
        if (tid < BK) Ms[tid] = pad_mask[b * S_LEN + kt * BK + tid] * (-1.0e9f);
        __syncthreads();

        // Scores: 4x4 microtile over d=32.
        float s[4][4] = {{0.f}};
        #pragma unroll
        for (int d = 0; d < DIM_HEAD; d += 4) {
            float4 q[4], kk[4];
            #pragma unroll
            for (int j = 0; j < 4; j++) {
                q[j]  = *reinterpret_cast<const float4*>(&Qs[qr0 + j][d]);
                kk[j] = *reinterpret_cast<const float4*>(&Ks[tx * 4 + j][d]);
            }
            #pragma unroll
            for (int i = 0; i < 4; i++)
                #pragma unroll
                for (int j = 0; j < 4; j++)
                    s[i][j] += q[i].x * kk[j].x + q[i].y * kk[j].y
                             + q[i].z * kk[j].z + q[i].w * kk[j].w;
        }

        // mask-before-scale (faithful to reference), online softmax.
        #pragma unroll
        for (int i = 0; i < 4; i++) {
            #pragma unroll
            for (int j = 0; j < 4; j++)
                s[i][j] = (s[i][j] + Ms[tx * 4 + j]) * SM_SCALE;

            float rm = fmaxf(fmaxf(s[i][0], s[i][1]), fmaxf(s[i][2], s[i][3]));
            #pragma unroll
            for (int off = 8; off > 0; off >>= 1)
                rm = fmaxf(rm, __shfl_xor_sync(0xffffffffu, rm, off, 16));

            const float mnew  = fmaxf(m[i], rm);
            const float alpha = __expf(m[i] - mnew);
            float rs = 0.f;
            #pragma unroll
            for (int j = 0; j < 4; j++) {
                s[i][j] = __expf(s[i][j] - mnew);
                rs += s[i][j];
            }
            #pragma unroll
            for (int off = 8; off > 0; off >>= 1)
                rs += __shfl_xor_sync(0xffffffffu, rs, off, 16);

            l[i] = l[i] * alpha + rs;
            O[i][0] *= alpha;
            O[i][1] *= alpha;
            m[i] = mnew;

            *reinterpret_cast<float4*>(&Ps[qr0 + i][tx * 4]) =
                make_float4(s[i][0], s[i][1], s[i][2], s[i][3]);
        }
        __syncthreads();

        // PV: O[r][d0..d0+1] += sum_k P[r][k] * V[k][d]
        #pragma unroll 8
        for (int k = 0; k < BK; k++) {
            const float2 v = *reinterpret_cast<const float2*>(&Vs[k][d0]);
            #pragma unroll
            for (int i = 0; i < 4; i++) {
                const float pp = Ps[qr0 + i][k];
                O[i][0] += pp * v.x;
                O[i][1] += pp * v.y;
            }
        }
        __syncthreads();
    }

    // Epilogue: normalize and store [B,H,S,Dh].
    #pragma unroll
    for (int i = 0; i < 4; i++) {
        const float inv = 1.0f / l[i];
        const size_t row = head_base + (size_t)(qt * BQ + qr0 + i) * DIM_HEAD;
        g_o[row + d0]     = O[i][0] * inv;
        g_o[row + d0 + 1] = O[i][1] * inv;
    }
}

// ---------------------------------------------------------------------------
// Kernel 3: residual + LayerNorm. grid = B*S blocks, 256 threads (one per dim).
// ---------------------------------------------------------------------------
__global__ void ln_kernel(const float* __restrict__ x,
                          const float* __restrict__ gamma,
                          const float* __restrict__ beta,
                          float* __restrict__ out) {
    const int row = blockIdx.x;          // b*S + s
    const int d   = threadIdx.x;
    const int b   = row / S_LEN;
    const int s   = row - b * S_LEN;

    const float attn = g_o[(((size_t)(b * NUM_HEADS + (d >> 5))) * S_LEN + s) * DIM_HEAD + (d & 31)];
    const float val  = attn + x[(size_t)row * D_MODEL + d];

    float sum = val, sq = val * val;
    #pragma unroll
    for (int off = 16; off > 0; off >>= 1) {
        sum += __shfl_xor_sync(0xffffffffu, sum, off);
        sq  += __shfl_xor_sync(0xffffffffu, sq, off);
    }
    __shared__ float ra[8], rb[8];
    const int w = threadIdx.x >> 5, lane = threadIdx.x & 31;
    if (lane == 0) { ra[w] = sum; rb[w] = sq; }
    __syncthreads();
    if (threadIdx.x == 0) {
        float sa = 0.f, sb = 0.f;
        #pragma unroll
        for (int i = 0; i < 8; i++) { sa += ra[i]; sb += rb[i]; }
        ra[0] = sa; rb[0] = sb;
    }
    __syncthreads();
    const float mu  = ra[0] * (1.0f / D_MODEL);
    const float var = rb[0] * (1.0f / D_MODEL) - mu * mu;
    out[(size_t)row * D_MODEL + d] = gamma[d] * (val - mu) * rsqrtf(var + LN_EPS) + beta[d];
}

// ---------------------------------------------------------------------------
// Launch
// ---------------------------------------------------------------------------
extern "C" void kernel_launch(void* const* d_in, const int* in_sizes, int n_in,
                              void* d_out, int out_size) {
    const float* x     = (const float*)d_in[0];
    const float* pad   = (const float*)d_in[1];
    const float* Wq    = (const float*)d_in[2];
    const float* bq    = (const float*)d_in[3];
    const float* Wk    = (const float*)d_in[4];
    const float* bk    = (const float*)d_in[5];
    const float* Wv    = (const float*)d_in[6];
    const float* bv    = (const float*)d_in[7];
    const float* gamma = (const float*)d_in[8];
    const float* beta  = (const float*)d_in[9];

    const int B = in_sizes[1] / S_LEN;   // pad_mask is [B, S]
    const int N = B * S_LEN;

    qkv_kernel<<<dim3(N / 32, 3), 256>>>(x, Wq, bq, Wk, bk, Wv, bv);
    attn_kernel<<<dim3(S_LEN / BQ, NUM_HEADS, B), 256>>>(pad);
    ln_kernel<<<N, 256>>>(x, gamma, beta, (float*)d_out);
}

// round 2
// speedup vs baseline: 3.8598x; 3.8598x over previous
#include <cuda_runtime.h>
#include <math.h>
#include <stdint.h>

#define D_MODEL   256
#define NUM_HEADS 8
#define DIM_HEAD  32
#define S_LEN     4096
#define MAX_B     2
#define LN_EPS    1e-6f
#define FULL_MASK 0xffffffffu
#define SM_SCALE  0.1767766952966369f  // 1/sqrt(32)

// Scratch (allocation-free rule: device globals)
__device__ float g_q[MAX_B * NUM_HEADS * S_LEN * DIM_HEAD];
__device__ float g_k[MAX_B * NUM_HEADS * S_LEN * DIM_HEAD];
__device__ float g_v[MAX_B * NUM_HEADS * S_LEN * DIM_HEAD];
__device__ float g_o[MAX_B * NUM_HEADS * S_LEN * DIM_HEAD];

// ---------------------------------------------------------------------------
// Helpers: tf32 convert + mma.sync m16n8k8 tf32
// ---------------------------------------------------------------------------
__device__ __forceinline__ uint32_t f2tf32(float x) {
    uint32_t r;
    asm("cvt.rna.tf32.f32 %0, %1;" : "=r"(r) : "f"(x));
    return r;
}
__device__ __forceinline__ float f2tf32f(float x) {
    return __uint_as_float(f2tf32(x));
}
__device__ __forceinline__ void mma_tf32(float c[4],
                                         uint32_t a0, uint32_t a1, uint32_t a2, uint32_t a3,
                                         uint32_t b0, uint32_t b1) {
    asm volatile(
        "mma.sync.aligned.m16n8k8.row.col.f32.tf32.tf32.f32 "
        "{%0,%1,%2,%3},{%4,%5,%6,%7},{%8,%9},{%0,%1,%2,%3};"
        : "+f"(c[0]), "+f"(c[1]), "+f"(c[2]), "+f"(c[3])
        : "r"(a0), "r"(a1), "r"(a2), "r"(a3), "r"(b0), "r"(b1));
}

// ---------------------------------------------------------------------------
// Kernel 1: QKV projection. out = x @ W + b, written as [B,H,S,Dh].
// ---------------------------------------------------------------------------
__global__ void qkv_kernel(const float* __restrict__ x,
                           const float* __restrict__ Wq, const float* __restrict__ bq,
                           const float* __restrict__ Wk, const float* __restrict__ bk,
                           const float* __restrict__ Wv, const float* __restrict__ bv) {
    __shared__ float xs[32][D_MODEL];

    const float* W;
    const float* bias;
    float* out;
    if (blockIdx.y == 0)      { W = Wq; bias = bq; out = g_q; }
    else if (blockIdx.y == 1) { W = Wk; bias = bk; out = g_k; }
    else                      { W = Wv; bias = bv; out = g_v; }

    const int n0  = blockIdx.x * 32;
    const int tid = threadIdx.x;

    {
        const float4* xsrc = reinterpret_cast<const float4*>(x + (size_t)n0 * D_MODEL);
        float4* xdst = reinterpret_cast<float4*>(&xs[0][0]);
        #pragma unroll
        for (int i = tid; i < 32 * D_MODEL / 4; i += 256) xdst[i] = xsrc[i];
    }
    __syncthreads();

    const int cg = (tid & 63) * 4;
    const int rg = (tid >> 6) * 8;

    float acc[8][4];
    {
        const float4 bb = *reinterpret_cast<const float4*>(&bias[cg]);
        #pragma unroll
        for (int j = 0; j < 8; j++) {
            acc[j][0] = bb.x; acc[j][1] = bb.y; acc[j][2] = bb.z; acc[j][3] = bb.w;
        }
    }

    #pragma unroll 4
    for (int k = 0; k < D_MODEL; k += 4) {
        const float4 w0 = *reinterpret_cast<const float4*>(&W[(k + 0) * D_MODEL + cg]);
        const float4 w1 = *reinterpret_cast<const float4*>(&W[(k + 1) * D_MODEL + cg]);
        const float4 w2 = *reinterpret_cast<const float4*>(&W[(k + 2) * D_MODEL + cg]);
        const float4 w3 = *reinterpret_cast<const float4*>(&W[(k + 3) * D_MODEL + cg]);
        #pragma unroll
        for (int j = 0; j < 8; j++) {
            const float4 xv = *reinterpret_cast<const float4*>(&xs[rg + j][k]);
            acc[j][0] += xv.x * w0.x + xv.y * w1.x + xv.z * w2.x + xv.w * w3.x;
            acc[j][1] += xv.x * w0.y + xv.y * w1.y + xv.z * w2.y + xv.w * w3.y;
            acc[j][2] += xv.x * w0.z + xv.y * w1.z + xv.z * w2.z + xv.w * w3.z;
            acc[j][3] += xv.x * w0.w + xv.y * w1.w + xv.z * w2.w + xv.w * w3.w;
        }
    }

    const int h  = cg >> 5;
    const int dh = cg & 31;
    #pragma unroll
    for (int j = 0; j < 8; j++) {
        const int n = n0 + rg + j;
        const int b = n / S_LEN;
        const int s = n - b * S_LEN;
        float4 v = make_float4(acc[j][0], acc[j][1], acc[j][2], acc[j][3]);
        *reinterpret_cast<float4*>(
            &out[(((size_t)(b * NUM_HEADS + h)) * S_LEN + s) * DIM_HEAD + dh]) = v;
    }
}

// ---------------------------------------------------------------------------
// Kernel 2: flash attention with tensor cores (mma.sync tf32).
// grid = (S/128, H, B), block = 256 (8 warps). Each warp: 16 q-rows.
// BK = 64 keys per iteration, K/V tiles in smem (pad 36 -> conflict-free B).
// ---------------------------------------------------------------------------
__global__ void __launch_bounds__(256, 2)
attn_mma_kernel(const float* __restrict__ pad_mask) {
    __shared__ float Ks[64][36];
    __shared__ float Vs[64][36];
    __shared__ float Ms[64];

    const int tid  = threadIdx.x;
    const int warp = tid >> 5;
    const int lane = tid & 31;
    const int r    = lane >> 2;   // 0..7
    const int qq   = lane & 3;    // 0..3

    const int qt = blockIdx.x, h = blockIdx.y, b = blockIdx.z;
    const size_t base = ((size_t)(b * NUM_HEADS + h)) * S_LEN * DIM_HEAD;
    const int q0 = qt * 128 + warp * 16;

    // Q fragments (A of m16n8k8), rows q0..q0+15, k = 32 dims -> 4 k-tiles.
    uint32_t qa[4][4];
    {
        const float* Qp = g_q + base + (size_t)q0 * DIM_HEAD;
        #pragma unroll
        for (int t = 0; t < 4; t++) {
            qa[t][0] = f2tf32(Qp[(r    ) * 32 + t * 8 + qq    ]);
            qa[t][1] = f2tf32(Qp[(r + 8) * 32 + t * 8 + qq    ]);
            qa[t][2] = f2tf32(Qp[(r    ) * 32 + t * 8 + qq + 4]);
            qa[t][3] = f2tf32(Qp[(r + 8) * 32 + t * 8 + qq + 4]);
        }
    }

    float oa[4][4];
    #pragma unroll
    for (int n = 0; n < 4; n++)
        #pragma unroll
        for (int i = 0; i < 4; i++) oa[n][i] = 0.f;

    float m0 = -1e30f, m1 = -1e30f, l0 = 0.f, l1 = 0.f;

    for (int kt = 0; kt < S_LEN / 64; kt++) {
        const float* Kp = g_k + base + (size_t)kt * 64 * DIM_HEAD;
        const float* Vp = g_v + base + (size_t)kt * 64 * DIM_HEAD;

        // Stage K,V (64x32) into smem, rounded to tf32 (float4 in/out; pad 36 keeps
        // 16B alignment since offsets stay multiples of 4 floats).
        #pragma unroll
        for (int i = tid; i < 64 * 8; i += 256) {
            const int rr = i >> 3, cc = (i & 7) * 4;
            float4 kv = *reinterpret_cast<const float4*>(&Kp[rr * 32 + cc]);
            kv.x = f2tf32f(kv.x); kv.y = f2tf32f(kv.y);
            kv.z = f2tf32f(kv.z); kv.w = f2tf32f(kv.w);
            *reinterpret_cast<float4*>(&Ks[rr][cc]) = kv;
            float4 vv = *reinterpret_cast<const float4*>(&Vp[rr * 32 + cc]);
            vv.x = f2tf32f(vv.x); vv.y = f2tf32f(vv.y);
            vv.z = f2tf32f(vv.z); vv.w = f2tf32f(vv.w);
            *reinterpret_cast<float4*>(&Vs[rr][cc]) = vv;
        }
        if (tid < 64)
            Ms[tid] = pad_mask[b * S_LEN + kt * 64 + tid] * (-1.0e9f * SM_SCALE);
        __syncthreads();

        // ---- scores: S[16,64] = Q[16,32] K^T, 8 n-tiles x 4 k-tiles ----
        float sc[8][4];
        #pragma unroll
        for (int j = 0; j < 8; j++) {
            sc[j][0] = 0.f; sc[j][1] = 0.f; sc[j][2] = 0.f; sc[j][3] = 0.f;
            #pragma unroll
            for (int t = 0; t < 4; t++) {
                const uint32_t b0 = __float_as_uint(Ks[j * 8 + r][t * 8 + qq]);
                const uint32_t b1 = __float_as_uint(Ks[j * 8 + r][t * 8 + qq + 4]);
                mma_tf32(sc[j], qa[t][0], qa[t][1], qa[t][2], qa[t][3], b0, b1);
            }
        }

        // ---- mask + scale + online softmax (rows r and r+8) ----
        float mx0 = -1e30f, mx1 = -1e30f;
        #pragma unroll
        for (int j = 0; j < 8; j++) {
            const float2 mb = *reinterpret_cast<const float2*>(&Ms[j * 8 + qq * 2]);
            sc[j][0] = fmaf(sc[j][0], SM_SCALE, mb.x);
            sc[j][1] = fmaf(sc[j][1], SM_SCALE, mb.y);
            sc[j][2] = fmaf(sc[j][2], SM_SCALE, mb.x);
            sc[j][3] = fmaf(sc[j][3], SM_SCALE, mb.y);
            mx0 = fmaxf(mx0, fmaxf(sc[j][0], sc[j][1]));
            mx1 = fmaxf(mx1, fmaxf(sc[j][2], sc[j][3]));
        }
        mx0 = fmaxf(mx0, __shfl_xor_sync(FULL_MASK, mx0, 1));
        mx0 = fmaxf(mx0, __shfl_xor_sync(FULL_MASK, mx0, 2));
        mx1 = fmaxf(mx1, __shfl_xor_sync(FULL_MASK, mx1, 1));
        mx1 = fmaxf(mx1, __shfl_xor_sync(FULL_MASK, mx1, 2));

        const float mn0 = fmaxf(m0, mx0);
        const float mn1 = fmaxf(m1, mx1);
        const float al0 = __expf(m0 - mn0);
        const float al1 = __expf(m1 - mn1);
        m0 = mn0; m1 = mn1;

        float s0 = 0.f, s1 = 0.f;
        #pragma unroll
        for (int j = 0; j < 8; j++) {
            sc[j][0] = __expf(sc[j][0] - mn0);
            sc[j][1] = __expf(sc[j][1] - mn0);
            sc[j][2] = __expf(sc[j][2] - mn1);
            sc[j][3] = __expf(sc[j][3] - mn1);
            s0 += sc[j][0] + sc[j][1];
            s1 += sc[j][2] + sc[j][3];
        }
        s0 += __shfl_xor_sync(FULL_MASK, s0, 1);
        s0 += __shfl_xor_sync(FULL_MASK, s0, 2);
        s1 += __shfl_xor_sync(FULL_MASK, s1, 1);
        s1 += __shfl_xor_sync(FULL_MASK, s1, 2);
        l0 = l0 * al0 + s0;
        l1 = l1 * al1 + s1;

        #pragma unroll
        for (int n = 0; n < 4; n++) {
            oa[n][0] *= al0; oa[n][1] *= al0;
            oa[n][2] *= al1; oa[n][3] *= al1;
        }

        // ---- PV: O[16,32] += P[16,64] V[64,32] ----
        // Convert P C-fragments -> A-fragments via quad shuffles, tile by tile.
        const int sl1 = (lane & ~3) | (qq >> 1);
        const int sl2 = sl1 + 2;
        #pragma unroll
        for (int j = 0; j < 8; j++) {
            const uint32_t p0 = f2tf32(sc[j][0]);
            const uint32_t p1 = f2tf32(sc[j][1]);
            const uint32_t p2 = f2tf32(sc[j][2]);
            const uint32_t p3 = f2tf32(sc[j][3]);
            const uint32_t x0 = __shfl_sync(FULL_MASK, p0, sl1);
            const uint32_t x1 = __shfl_sync(FULL_MASK, p1, sl1);
            const uint32_t x2 = __shfl_sync(FULL_MASK, p2, sl1);
            const uint32_t x3 = __shfl_sync(FULL_MASK, p3, sl1);
            const uint32_t y0 = __shfl_sync(FULL_MASK, p0, sl2);
            const uint32_t y1 = __shfl_sync(FULL_MASK, p1, sl2);
            const uint32_t y2 = __shfl_sync(FULL_MASK, p2, sl2);
            const uint32_t y3 = __shfl_sync(FULL_MASK, p3, sl2);
            const uint32_t a0 = (qq & 1) ? x1 : x0;
            const uint32_t a1 = (qq & 1) ? x3 : x2;
            const uint32_t a2 = (qq & 1) ? y1 : y0;
            const uint32_t a3 = (qq & 1) ? y3 : y2;
            #pragma unroll
            for (int n = 0; n < 4; n++) {
                const uint32_t b0 = __float_as_uint(Vs[j * 8 + qq    ][n * 8 + r]);
                const uint32_t b1 = __float_as_uint(Vs[j * 8 + qq + 4][n * 8 + r]);
                mma_tf32(oa[n], a0, a1, a2, a3, b0, b1);
            }
        }
        __syncthreads();
    }

    // Epilogue: normalize and store [B,H,S,Dh].
    const float i0 = 1.0f / l0;
    const float i1 = 1.0f / l1;
    float* Op = g_o + base + (size_t)q0 * DIM_HEAD;
    #pragma unroll
    for (int n = 0; n < 4; n++) {
        *reinterpret_cast<float2*>(&Op[(r    ) * 32 + n * 8 + qq * 2]) =
            make_float2(oa[n][0] * i0, oa[n][1] * i0);
        *reinterpret_cast<float2*>(&Op[(r + 8) * 32 + n * 8 + qq * 2]) =
            make_float2(oa[n][2] * i1, oa[n][3] * i1);
    }
}

// ---------------------------------------------------------------------------
// Kernel 3: residual + LayerNorm. grid = B*S blocks, 256 threads.
// ---------------------------------------------------------------------------
__global__ void ln_kernel(const float* __restrict__ x,
                          const float* __restrict__ gamma,
                          const float* __restrict__ beta,
                          float* __restrict__ out) {
    const int row = blockIdx.x;
    const int d   = threadIdx.x;
    const int b   = row / S_LEN;
    const int s   = row - b * S_LEN;

    const float attn = g_o[(((size_t)(b * NUM_HEADS + (d >> 5))) * S_LEN + s) * DIM_HEAD + (d & 31)];
    const float val  = attn + x[(size_t)row * D_MODEL + d];

    float sum = val, sq = val * val;
    #pragma unroll
    for (int off = 16; off > 0; off >>= 1) {
        sum += __shfl_xor_sync(FULL_MASK, sum, off);
        sq  += __shfl_xor_sync(FULL_MASK, sq, off);
    }
    __shared__ float ra[8], rb[8];
    const int w = threadIdx.x >> 5, lane = threadIdx.x & 31;
    if (lane == 0) { ra[w] = sum; rb[w] = sq; }
    __syncthreads();
    if (threadIdx.x == 0) {
        float sa = 0.f, sb = 0.f;
        #pragma unroll
        for (int i = 0; i < 8; i++) { sa += ra[i]; sb += rb[i]; }
        ra[0] = sa; rb[0] = sb;
    }
    __syncthreads();
    const float mu  = ra[0] * (1.0f / D_MODEL);
    const float var = rb[0] * (1.0f / D_MODEL) - mu * mu;
    out[(size_t)row * D_MODEL + d] = gamma[d] * (val - mu) * rsqrtf(var + LN_EPS) + beta[d];
}

// ---------------------------------------------------------------------------
// Launch
// ---------------------------------------------------------------------------
extern "C" void kernel_launch(void* const* d_in, const int* in_sizes, int n_in,
                              void* d_out, int out_size) {
    const float* x     = (const float*)d_in[0];
    const float* pad   = (const float*)d_in[1];
    const float* Wq    = (const float*)d_in[2];
    const float* bq    = (const float*)d_in[3];
    const float* Wk    = (const float*)d_in[4];
    const float* bk    = (const float*)d_in[5];
    const float* Wv    = (const float*)d_in[6];
    const float* bv    = (const float*)d_in[7];
    const float* gamma = (const float*)d_in[8];
    const float* beta  = (const float*)d_in[9];

    const int B = in_sizes[1] / S_LEN;   // pad_mask is [B, S]
    const int N = B * S_LEN;

    qkv_kernel<<<dim3(N / 32, 3), 256>>>(x, Wq, bq, Wk, bk, Wv, bv);
    attn_mma_kernel<<<dim3(S_LEN / 128, NUM_HEADS, B), 256>>>(pad);
    ln_kernel<<<N, 256>>>(x, gamma, beta, (float*)d_out);
}

// round 3
// speedup vs baseline: 5.9613x; 1.5445x over previous
#include <cuda_runtime.h>
#include <math.h>
#include <stdint.h>

#define D_MODEL   256
#define NUM_HEADS 8
#define DIM_HEAD  32
#define S_LEN     4096
#define MAX_B     2
#define LN_EPS    1e-6f
#define FULL_MASK 0xffffffffu
#define SM_SCALE  0.1767766952966369f  // 1/sqrt(32)

// bf16 scratch stored as packed words (alignment + allocation-free rule).
// g_q, g_k: [B,H,S,32] bf16 -> 16 words per row.
// g_v:      [B,H,32,S] bf16 (transposed) -> 2048 words per dim-row.
__device__ uint32_t g_q[MAX_B * NUM_HEADS * S_LEN * DIM_HEAD / 2];
__device__ uint32_t g_k[MAX_B * NUM_HEADS * S_LEN * DIM_HEAD / 2];
__device__ uint32_t g_v[MAX_B * NUM_HEADS * S_LEN * DIM_HEAD / 2];
__device__ float    g_o[MAX_B * NUM_HEADS * S_LEN * DIM_HEAD];

// ---------------------------------------------------------------------------
// Helpers
// ---------------------------------------------------------------------------
__device__ __forceinline__ uint32_t pack_bf16(float lo, float hi) {
    uint32_t r;
    asm("cvt.rn.bf16x2.f32 %0, %1, %2;" : "=r"(r) : "f"(hi), "f"(lo));
    return r;
}
__device__ __forceinline__ void mma_bf16(float c[4],
                                         uint32_t a0, uint32_t a1, uint32_t a2, uint32_t a3,
                                         uint32_t b0, uint32_t b1) {
    asm volatile(
        "mma.sync.aligned.m16n8k16.row.col.f32.bf16.bf16.f32 "
        "{%0,%1,%2,%3},{%4,%5,%6,%7},{%8,%9},{%0,%1,%2,%3};"
        : "+f"(c[0]), "+f"(c[1]), "+f"(c[2]), "+f"(c[3])
        : "r"(a0), "r"(a1), "r"(a2), "r"(a3), "r"(b0), "r"(b1));
}

// ---------------------------------------------------------------------------
// Kernel 1: QKV projection (fp32 SIMT), bf16 outputs.
// Q,K written [B,H,S,Dh]; V written transposed [B,H,Dh,S].
// grid = (N/32, 3), block = 256. Thread microtile: 8 rows x 4 cols.
// ---------------------------------------------------------------------------
__global__ void qkv_kernel(const float* __restrict__ x,
                           const float* __restrict__ Wq, const float* __restrict__ bq,
                           const float* __restrict__ Wk, const float* __restrict__ bk,
                           const float* __restrict__ Wv, const float* __restrict__ bv) {
    __shared__ float xs[32][D_MODEL];

    const float* W;
    const float* bias;
    if (blockIdx.y == 0)      { W = Wq; bias = bq; }
    else if (blockIdx.y == 1) { W = Wk; bias = bk; }
    else                      { W = Wv; bias = bv; }

    const int n0  = blockIdx.x * 32;
    const int tid = threadIdx.x;

    {
        const float4* xsrc = reinterpret_cast<const float4*>(x + (size_t)n0 * D_MODEL);
        float4* xdst = reinterpret_cast<float4*>(&xs[0][0]);
        #pragma unroll
        for (int i = tid; i < 32 * D_MODEL / 4; i += 256) xdst[i] = xsrc[i];
    }
    __syncthreads();

    const int cg = (tid & 63) * 4;
    const int rg = (tid >> 6) * 8;

    float acc[8][4];
    {
        const float4 bb = *reinterpret_cast<const float4*>(&bias[cg]);
        #pragma unroll
        for (int j = 0; j < 8; j++) {
            acc[j][0] = bb.x; acc[j][1] = bb.y; acc[j][2] = bb.z; acc[j][3] = bb.w;
        }
    }

    #pragma unroll 4
    for (int k = 0; k < D_MODEL; k += 4) {
        const float4 w0 = *reinterpret_cast<const float4*>(&W[(k + 0) * D_MODEL + cg]);
        const float4 w1 = *reinterpret_cast<const float4*>(&W[(k + 1) * D_MODEL + cg]);
        const float4 w2 = *reinterpret_cast<const float4*>(&W[(k + 2) * D_MODEL + cg]);
        const float4 w3 = *reinterpret_cast<const float4*>(&W[(k + 3) * D_MODEL + cg]);
        #pragma unroll
        for (int j = 0; j < 8; j++) {
            const float4 xv = *reinterpret_cast<const float4*>(&xs[rg + j][k]);
            acc[j][0] += xv.x * w0.x + xv.y * w1.x + xv.z * w2.x + xv.w * w3.x;
            acc[j][1] += xv.x * w0.y + xv.y * w1.y + xv.z * w2.y + xv.w * w3.y;
            acc[j][2] += xv.x * w0.z + xv.y * w1.z + xv.z * w2.z + xv.w * w3.z;
            acc[j][3] += xv.x * w0.w + xv.y * w1.w + xv.z * w2.w + xv.w * w3.w;
        }
    }

    const int h  = cg >> 5;
    const int dh = cg & 31;
    const int n  = n0 + rg;          // 8 consecutive rows, same batch (4096 % 32 == 0)
    const int b  = n / S_LEN;
    const int s0 = n - b * S_LEN;
    const int bh = b * NUM_HEADS + h;

    if (blockIdx.y == 2) {
        // V transposed: g_v[bh][dh+jj][s0..s0+7]
        #pragma unroll
        for (int jj = 0; jj < 4; jj++) {
            uint4 v;
            v.x = pack_bf16(acc[0][jj], acc[1][jj]);
            v.y = pack_bf16(acc[2][jj], acc[3][jj]);
            v.z = pack_bf16(acc[4][jj], acc[5][jj]);
            v.w = pack_bf16(acc[6][jj], acc[7][jj]);
            *reinterpret_cast<uint4*>(
                &g_v[((size_t)bh * DIM_HEAD + dh + jj) * (S_LEN / 2) + (s0 >> 1)]) = v;
        }
    } else {
        uint32_t* out = (blockIdx.y == 0) ? g_q : g_k;
        #pragma unroll
        for (int j = 0; j < 8; j++) {
            uint2 v;
            v.x = pack_bf16(acc[j][0], acc[j][1]);
            v.y = pack_bf16(acc[j][2], acc[j][3]);
            *reinterpret_cast<uint2*>(
                &out[((size_t)bh * S_LEN + s0 + j) * 16 + (dh >> 1)]) = v;
        }
    }
}

// ---------------------------------------------------------------------------
// Kernel 2: flash attention, bf16 mma.m16n8k16.
// grid = (S/128, H, B), block = 256 (8 warps, 16 q-rows each). BK = 64.
// Ks: [key][dim-pair] words, stride 20 (banks 20r+qq conflict-free).
// Vs: [dim][key-pair] words, stride 36 (banks 4r+qq conflict-free).
// P C-frags map directly onto bf16 A-frags: zero shuffles in PV.
// ---------------------------------------------------------------------------
__global__ void __launch_bounds__(256, 2)
attn_mma_kernel(const float* __restrict__ pad_mask) {
    __shared__ uint32_t Ks[64][20];
    __shared__ uint32_t Vs[32][36];
    __shared__ float    Ms[64];

    const int tid  = threadIdx.x;
    const int warp = tid >> 5;
    const int lane = tid & 31;
    const int r    = lane >> 2;   // 0..7
    const int qq   = lane & 3;    // 0..3

    const int qt = blockIdx.x, h = blockIdx.y, b = blockIdx.z;
    const int bh = b * NUM_HEADS + h;
    const int q0 = qt * 128 + warp * 16;

    // Q fragments: 2 k-chunks of 16 dims, m16n8k16 A layout.
    uint32_t qa[2][4];
    {
        const uint32_t* Qw = g_q + ((size_t)bh * S_LEN + q0) * 16;
        #pragma unroll
        for (int t = 0; t < 2; t++) {
            qa[t][0] = Qw[(r    ) * 16 + t * 8 + qq    ];
            qa[t][1] = Qw[(r + 8) * 16 + t * 8 + qq    ];
            qa[t][2] = Qw[(r    ) * 16 + t * 8 + qq + 4];
            qa[t][3] = Qw[(r + 8) * 16 + t * 8 + qq + 4];
        }
    }

    float oa[4][4];
    #pragma unroll
    for (int nn = 0; nn < 4; nn++)
        #pragma unroll
        for (int i = 0; i < 4; i++) oa[nn][i] = 0.f;

    float m0 = -1e30f, m1 = -1e30f, l0 = 0.f, l1 = 0.f;

    const uint32_t* Kw = g_k + (size_t)bh * S_LEN * 16;
    const uint32_t* Vw = g_v + (size_t)bh * DIM_HEAD * (S_LEN / 2);

    for (int kt = 0; kt < S_LEN / 64; kt++) {
        // ---- stage K (64x32 bf16 = 1024 words) and V-transposed (32x64) ----
        {
            const uint4 kv = *reinterpret_cast<const uint4*>(&Kw[kt * 1024 + tid * 4]);
            *reinterpret_cast<uint4*>(&Ks[tid >> 2][(tid & 3) * 4]) = kv;
            const uint4 vv = *reinterpret_cast<const uint4*>(
                &Vw[(tid >> 3) * (S_LEN / 2) + kt * 32 + (tid & 7) * 4]);
            *reinterpret_cast<uint4*>(&Vs[tid >> 3][(tid & 7) * 4]) = vv;
            if (tid < 64)
                Ms[tid] = pad_mask[b * S_LEN + kt * 64 + tid] * (-1.0e9f * SM_SCALE);
        }
        __syncthreads();

        // ---- scores: S[16,64] = Q K^T, 8 n-tiles x 2 k-chunks ----
        float sc[8][4];
        #pragma unroll
        for (int j = 0; j < 8; j++) {
            sc[j][0] = 0.f; sc[j][1] = 0.f; sc[j][2] = 0.f; sc[j][3] = 0.f;
            #pragma unroll
            for (int t = 0; t < 2; t++) {
                const uint32_t b0 = Ks[j * 8 + r][t * 8 + qq];
                const uint32_t b1 = Ks[j * 8 + r][t * 8 + qq + 4];
                mma_bf16(sc[j], qa[t][0], qa[t][1], qa[t][2], qa[t][3], b0, b1);
            }
        }

        // ---- mask + scale + online softmax ----
        float mx0 = -1e30f, mx1 = -1e30f;
        #pragma unroll
        for (int j = 0; j < 8; j++) {
            const float2 mb = *reinterpret_cast<const float2*>(&Ms[j * 8 + qq * 2]);
            sc[j][0] = fmaf(sc[j][0], SM_SCALE, mb.x);
            sc[j][1] = fmaf(sc[j][1], SM_SCALE, mb.y);
            sc[j][2] = fmaf(sc[j][2], SM_SCALE, mb.x);
            sc[j][3] = fmaf(sc[j][3], SM_SCALE, mb.y);
            mx0 = fmaxf(mx0, fmaxf(sc[j][0], sc[j][1]));
            mx1 = fmaxf(mx1, fmaxf(sc[j][2], sc[j][3]));
        }
        mx0 = fmaxf(mx0, __shfl_xor_sync(FULL_MASK, mx0, 1));
        mx0 = fmaxf(mx0, __shfl_xor_sync(FULL_MASK, mx0, 2));
        mx1 = fmaxf(mx1, __shfl_xor_sync(FULL_MASK, mx1, 1));
        mx1 = fmaxf(mx1, __shfl_xor_sync(FULL_MASK, mx1, 2));

        const float mn0 = fmaxf(m0, mx0);
        const float mn1 = fmaxf(m1, mx1);
        const float al0 = __expf(m0 - mn0);
        const float al1 = __expf(m1 - mn1);
        m0 = mn0; m1 = mn1;

        float s0 = 0.f, s1 = 0.f;
        #pragma unroll
        for (int j = 0; j < 8; j++) {
            sc[j][0] = __expf(sc[j][0] - mn0);
            sc[j][1] = __expf(sc[j][1] - mn0);
            sc[j][2] = __expf(sc[j][2] - mn1);
            sc[j][3] = __expf(sc[j][3] - mn1);
            s0 += sc[j][0] + sc[j][1];
            s1 += sc[j][2] + sc[j][3];
        }
        s0 += __shfl_xor_sync(FULL_MASK, s0, 1);
        s0 += __shfl_xor_sync(FULL_MASK, s0, 2);
        s1 += __shfl_xor_sync(FULL_MASK, s1, 1);
        s1 += __shfl_xor_sync(FULL_MASK, s1, 2);
        l0 = l0 * al0 + s0;
        l1 = l1 * al1 + s1;

        #pragma unroll
        for (int nn = 0; nn < 4; nn++) {
            oa[nn][0] *= al0; oa[nn][1] *= al0;
            oa[nn][2] *= al1; oa[nn][3] *= al1;
        }

        // ---- PV: O[16,32] += P[16,64] V[64,32]; P C-frags -> A-frags by pack ----
        #pragma unroll
        for (int jp = 0; jp < 4; jp++) {
            const uint32_t a0 = pack_bf16(sc[2 * jp    ][0], sc[2 * jp    ][1]);
            const uint32_t a1 = pack_bf16(sc[2 * jp    ][2], sc[2 * jp    ][3]);
            const uint32_t a2 = pack_bf16(sc[2 * jp + 1][0], sc[2 * jp + 1][1]);
            const uint32_t a3 = pack_bf16(sc[2 * jp + 1][2], sc[2 * jp + 1][3]);
            #pragma unroll
            for (int nn = 0; nn < 4; nn++) {
                const uint32_t b0 = Vs[nn * 8 + r][jp * 8 + qq];
                const uint32_t b1 = Vs[nn * 8 + r][jp * 8 + qq + 4];
                mma_bf16(oa[nn], a0, a1, a2, a3, b0, b1);
            }
        }
        __syncthreads();
    }

    // Epilogue: normalize, store fp32 [B,H,S,Dh].
    const float i0 = 1.0f / l0;
    const float i1 = 1.0f / l1;
    float* Op = g_o + ((size_t)bh * S_LEN + q0) * DIM_HEAD;
    #pragma unroll
    for (int nn = 0; nn < 4; nn++) {
        *reinterpret_cast<float2*>(&Op[(r    ) * 32 + nn * 8 + qq * 2]) =
            make_float2(oa[nn][0] * i0, oa[nn][1] * i0);
        *reinterpret_cast<float2*>(&Op[(r + 8) * 32 + nn * 8 + qq * 2]) =
            make_float2(oa[nn][2] * i1, oa[nn][3] * i1);
    }
}

// ---------------------------------------------------------------------------
// Kernel 3: residual + LayerNorm. grid = B*S blocks, 256 threads.
// ---------------------------------------------------------------------------
__global__ void ln_kernel(const float* __restrict__ x,
                          const float* __restrict__ gamma,
                          const float* __restrict__ beta,
                          float* __restrict__ out) {
    const int row = blockIdx.x;
    const int d   = threadIdx.x;
    const int b   = row / S_LEN;
    const int s   = row - b * S_LEN;

    const float attn = g_o[(((size_t)(b * NUM_HEADS + (d >> 5))) * S_LEN + s) * DIM_HEAD + (d & 31)];
    const float val  = attn + x[(size_t)row * D_MODEL + d];

    float sum = val, sq = val * val;
    #pragma unroll
    for (int off = 16; off > 0; off >>= 1) {
        sum += __shfl_xor_sync(FULL_MASK, sum, off);
        sq  += __shfl_xor_sync(FULL_MASK, sq, off);
    }
    __shared__ float ra[8], rb[8];
    const int w = threadIdx.x >> 5, lane = threadIdx.x & 31;
    if (lane == 0) { ra[w] = sum; rb[w] = sq; }
    __syncthreads();
    if (threadIdx.x == 0) {
        float sa = 0.f, sb = 0.f;
        #pragma unroll
        for (int i = 0; i < 8; i++) { sa += ra[i]; sb += rb[i]; }
        ra[0] = sa; rb[0] = sb;
    }
    __syncthreads();
    const float mu  = ra[0] * (1.0f / D_MODEL);
    const float var = rb[0] * (1.0f / D_MODEL) - mu * mu;
    out[(size_t)row * D_MODEL + d] = gamma[d] * (val - mu) * rsqrtf(var + LN_EPS) + beta[d];
}

// ---------------------------------------------------------------------------
// Launch
// ---------------------------------------------------------------------------
extern "C" void kernel_launch(void* const* d_in, const int* in_sizes, int n_in,
                              void* d_out, int out_size) {
    const float* x     = (const float*)d_in[0];
    const float* pad   = (const float*)d_in[1];
    const float* Wq    = (const float*)d_in[2];
    const float* bq    = (const float*)d_in[3];
    const float* Wk    = (const float*)d_in[4];
    const float* bk    = (const float*)d_in[5];
    const float* Wv    = (const float*)d_in[6];
    const float* bv    = (const float*)d_in[7];
    const float* gamma = (const float*)d_in[8];
    const float* beta  = (const float*)d_in[9];

    const int B = in_sizes[1] / S_LEN;   // pad_mask is [B, S]
    const int N = B * S_LEN;

    qkv_kernel<<<dim3(N / 32, 3), 256>>>(x, Wq, bq, Wk, bk, Wv, bv);
    attn_mma_kernel<<<dim3(S_LEN / 128, NUM_HEADS, B), 256>>>(pad);
    ln_kernel<<<N, 256>>>(x, gamma, beta, (float*)d_out);
}

// round 4
// speedup vs baseline: 9.5463x; 1.6014x over previous
#include <cuda_runtime.h>
#include <cuda_bf16.h>
#include <math.h>
#include <stdint.h>

#define D_MODEL   256
#define NUM_HEADS 8
#define DIM_HEAD  32
#define S_LEN     4096
#define MAX_B     2
#define LN_EPS    1e-6f
#define FULL_MASK 0xffffffffu
#define SM_SCALE  0.1767766952966369f      // 1/sqrt(32)
#define QK_SCALE  0.2550565405694324f      // SM_SCALE * log2(e)
#define MASK_LOG2 (-2.550565405694324e8f)  // -1e9 * SM_SCALE * log2(e)

// bf16 scratch stored as packed words.
// g_q (pre-scaled by QK_SCALE), g_k: [B,H,S,32] bf16 -> 16 words/row.
// g_v: [B,H,32,S] bf16 (transposed) -> 2048 words per dim-row.
__device__ uint32_t g_q[MAX_B * NUM_HEADS * S_LEN * DIM_HEAD / 2];
__device__ uint32_t g_k[MAX_B * NUM_HEADS * S_LEN * DIM_HEAD / 2];
__device__ uint32_t g_v[MAX_B * NUM_HEADS * S_LEN * DIM_HEAD / 2];
__device__ float    g_o[MAX_B * NUM_HEADS * S_LEN * DIM_HEAD];

// ---------------------------------------------------------------------------
// Helpers
// ---------------------------------------------------------------------------
__device__ __forceinline__ uint32_t pack_bf16(float lo, float hi) {
    uint32_t r;
    asm("cvt.rn.bf16x2.f32 %0, %1, %2;" : "=r"(r) : "f"(hi), "f"(lo));
    return r;
}
__device__ __forceinline__ float ex2f(float x) {
    float y;
    asm("ex2.approx.f32 %0, %1;" : "=f"(y) : "f"(x));
    return y;
}
__device__ __forceinline__ void mma_bf16(float c[4],
                                         uint32_t a0, uint32_t a1, uint32_t a2, uint32_t a3,
                                         uint32_t b0, uint32_t b1) {
    asm volatile(
        "mma.sync.aligned.m16n8k16.row.col.f32.bf16.bf16.f32 "
        "{%0,%1,%2,%3},{%4,%5,%6,%7},{%8,%9},{%0,%1,%2,%3};"
        : "+f"(c[0]), "+f"(c[1]), "+f"(c[2]), "+f"(c[3])
        : "r"(a0), "r"(a1), "r"(a2), "r"(a3), "r"(b0), "r"(b1));
}

// ---------------------------------------------------------------------------
// Kernel 1: QKV projection on tensor cores (bf16 mma, fp32 accum).
// grid = (rows/128, 4, 3), block = 256 (8 warps: 4 m-quarters x 2 n-halves).
// Block tile: 128 rows x 64 cols, K = 256 in chunks of 64 via smem.
// Warp tile: 32m x 32n -> 2 m-frags x 4 n-frags, 8 mma per k16-step.
// Q epilogue pre-scales by QK_SCALE; V epilogue transposes via smem bounce.
// ---------------------------------------------------------------------------
__global__ void __launch_bounds__(256, 2)
qkv_mma_kernel(const float* __restrict__ x,
               const float* __restrict__ Wq, const float* __restrict__ bq,
               const float* __restrict__ Wk, const float* __restrict__ bk,
               const float* __restrict__ Wv, const float* __restrict__ bv) {
    __shared__ __align__(16) uint32_t As[128][36];  // x tile, bf16 pairs along k
    __shared__ __align__(16) uint32_t Ws[64][36];   // W^T tile [n][k-word]

    const int z = blockIdx.z;
    const float* W;
    const float* bias;
    if (z == 0)      { W = Wq; bias = bq; }
    else if (z == 1) { W = Wk; bias = bk; }
    else             { W = Wv; bias = bv; }

    const int row0 = blockIdx.x * 128;
    const int n0   = blockIdx.y * 64;
    const int tid  = threadIdx.x;
    const int warp = tid >> 5, lane = tid & 31;
    const int r    = lane >> 2, qq = lane & 3;
    const int wm   = warp >> 1;   // 0..3
    const int wn   = warp & 1;    // 0..1

    float acc[2][4][4];
    #pragma unroll
    for (int mf = 0; mf < 2; mf++)
        #pragma unroll
        for (int nf = 0; nf < 4; nf++)
            #pragma unroll
            for (int i = 0; i < 4; i++) acc[mf][nf][i] = 0.f;

    for (int kc = 0; kc < 4; kc++) {
        const int k0 = kc * 64;
        // stage x[128 x 64] -> As (bf16 word pairs)
        #pragma unroll
        for (int w = 0; w < 8; w++) {
            const int idx = tid + w * 256;
            const int m = idx >> 4, ko = (idx & 15) * 4;
            const float4 f = *reinterpret_cast<const float4*>(
                &x[(size_t)(row0 + m) * D_MODEL + k0 + ko]);
            As[m][(ko >> 1)]     = pack_bf16(f.x, f.y);
            As[m][(ko >> 1) + 1] = pack_bf16(f.z, f.w);
        }
        // stage W^T[64 n x 32 kw]
        #pragma unroll
        for (int i = 0; i < 2; i++) {
            const int g  = tid + i * 256;
            const int kw = g >> 4, n4 = (g & 15) * 4;
            const float4 f0 = *reinterpret_cast<const float4*>(
                &W[(size_t)(k0 + 2 * kw) * D_MODEL + n0 + n4]);
            const float4 f1 = *reinterpret_cast<const float4*>(
                &W[(size_t)(k0 + 2 * kw + 1) * D_MODEL + n0 + n4]);
            Ws[n4    ][kw] = pack_bf16(f0.x, f1.x);
            Ws[n4 + 1][kw] = pack_bf16(f0.y, f1.y);
            Ws[n4 + 2][kw] = pack_bf16(f0.z, f1.z);
            Ws[n4 + 3][kw] = pack_bf16(f0.w, f1.w);
        }
        __syncthreads();

        #pragma unroll
        for (int ks = 0; ks < 4; ks++) {
            uint32_t a[2][4], bf[4][2];
            #pragma unroll
            for (int mf = 0; mf < 2; mf++) {
                const int mr = wm * 32 + mf * 16;
                a[mf][0] = As[mr + r    ][ks * 8 + qq];
                a[mf][1] = As[mr + r + 8][ks * 8 + qq];
                a[mf][2] = As[mr + r    ][ks * 8 + qq + 4];
                a[mf][3] = As[mr + r + 8][ks * 8 + qq + 4];
            }
            #pragma unroll
            for (int nf = 0; nf < 4; nf++) {
                const int nr = wn * 32 + nf * 8;
                bf[nf][0] = Ws[nr + r][ks * 8 + qq];
                bf[nf][1] = Ws[nr + r][ks * 8 + qq + 4];
            }
            #pragma unroll
            for (int mf = 0; mf < 2; mf++)
                #pragma unroll
                for (int nf = 0; nf < 4; nf++)
                    mma_bf16(acc[mf][nf], a[mf][0], a[mf][1], a[mf][2], a[mf][3],
                             bf[nf][0], bf[nf][1]);
        }
        __syncthreads();
    }

    const int b  = row0 >> 12;          // 4096 rows per batch
    const int s0 = row0 & (S_LEN - 1);

    if (z != 2) {
        uint32_t* out = (z == 0) ? g_q : g_k;
        const float scale = (z == 0) ? QK_SCALE : 1.0f;
        const int h  = (n0 >> 5) + wn;  // wn*32 cols = one head
        const int bh = b * NUM_HEADS + h;
        #pragma unroll
        for (int mf = 0; mf < 2; mf++) {
            const int s = s0 + wm * 32 + mf * 16;
            #pragma unroll
            for (int nf = 0; nf < 4; nf++) {
                const float2 bb = *reinterpret_cast<const float2*>(
                    &bias[n0 + wn * 32 + nf * 8 + qq * 2]);
                const float c0 = (acc[mf][nf][0] + bb.x) * scale;
                const float c1 = (acc[mf][nf][1] + bb.y) * scale;
                const float c2 = (acc[mf][nf][2] + bb.x) * scale;
                const float c3 = (acc[mf][nf][3] + bb.y) * scale;
                out[((size_t)bh * S_LEN + s + r    ) * 16 + nf * 4 + qq] = pack_bf16(c0, c1);
                out[((size_t)bh * S_LEN + s + r + 8) * 16 + nf * 4 + qq] = pack_bf16(c2, c3);
            }
        }
    } else {
        // V: transpose to [dh][s] via smem bounce (reuse As; rows padded to 136 halves)
        __nv_bfloat16* Vt = reinterpret_cast<__nv_bfloat16*>(&As[0][0]);
        #pragma unroll
        for (int mf = 0; mf < 2; mf++) {
            const int ml = wm * 32 + mf * 16;
            #pragma unroll
            for (int nf = 0; nf < 4; nf++) {
                const int nc = wn * 32 + nf * 8 + qq * 2;
                const float2 bb = *reinterpret_cast<const float2*>(&bias[n0 + nc]);
                Vt[(nc    ) * 136 + ml + r    ] = __float2bfloat16(acc[mf][nf][0] + bb.x);
                Vt[(nc + 1) * 136 + ml + r    ] = __float2bfloat16(acc[mf][nf][1] + bb.y);
                Vt[(nc    ) * 136 + ml + r + 8] = __float2bfloat16(acc[mf][nf][2] + bb.x);
                Vt[(nc + 1) * 136 + ml + r + 8] = __float2bfloat16(acc[mf][nf][3] + bb.y);
            }
        }
        __syncthreads();
        #pragma unroll
        for (int i = 0; i < 4; i++) {
            const int idx = tid + i * 256;
            const int n = idx >> 4, wq = (idx & 15) * 4;
            const uint4 val = *reinterpret_cast<const uint4*>(&Vt[n * 136 + wq * 2]);
            const int col = n0 + n;
            const int bh  = b * NUM_HEADS + (col >> 5);
            const int dh  = col & 31;
            *reinterpret_cast<uint4*>(
                &g_v[((size_t)bh * DIM_HEAD + dh) * (S_LEN / 2) + (s0 >> 1) + wq]) = val;
        }
    }
}

// ---------------------------------------------------------------------------
// Kernel 2: flash attention, bf16 mma, fixed-max softmax (exp2 domain).
// Q pre-scaled by QK_SCALE in qkv kernel; no running max, no rescaling.
// grid = (S/128, H, B), block = 256 (8 warps, 16 q-rows each). BK = 64.
// ---------------------------------------------------------------------------
__global__ void __launch_bounds__(256, 2)
attn_mma_kernel(const float* __restrict__ pad_mask) {
    __shared__ uint32_t Ks[64][20];
    __shared__ uint32_t Vs[32][36];
    __shared__ float    Ms[64];

    const int tid  = threadIdx.x;
    const int warp = tid >> 5;
    const int lane = tid & 31;
    const int r    = lane >> 2;
    const int qq   = lane & 3;

    const int qt = blockIdx.x, h = blockIdx.y, b = blockIdx.z;
    const int bh = b * NUM_HEADS + h;
    const int q0 = qt * 128 + warp * 16;

    uint32_t qa[2][4];
    {
        const uint32_t* Qw = g_q + ((size_t)bh * S_LEN + q0) * 16;
        #pragma unroll
        for (int t = 0; t < 2; t++) {
            qa[t][0] = Qw[(r    ) * 16 + t * 8 + qq    ];
            qa[t][1] = Qw[(r + 8) * 16 + t * 8 + qq    ];
            qa[t][2] = Qw[(r    ) * 16 + t * 8 + qq + 4];
            qa[t][3] = Qw[(r + 8) * 16 + t * 8 + qq + 4];
        }
    }

    float oa[4][4];
    #pragma unroll
    for (int nn = 0; nn < 4; nn++)
        #pragma unroll
        for (int i = 0; i < 4; i++) oa[nn][i] = 0.f;

    float l0 = 0.f, l1 = 0.f;   // per-lane partial sums (16 cols each)

    const uint32_t* Kw = g_k + (size_t)bh * S_LEN * 16;
    const uint32_t* Vw = g_v + (size_t)bh * DIM_HEAD * (S_LEN / 2);

    for (int kt = 0; kt < S_LEN / 64; kt++) {
        {
            const uint4 kv = *reinterpret_cast<const uint4*>(&Kw[kt * 1024 + tid * 4]);
            *reinterpret_cast<uint4*>(&Ks[tid >> 2][(tid & 3) * 4]) = kv;
            const uint4 vv = *reinterpret_cast<const uint4*>(
                &Vw[(tid >> 3) * (S_LEN / 2) + kt * 32 + (tid & 7) * 4]);
            *reinterpret_cast<uint4*>(&Vs[tid >> 3][(tid & 7) * 4]) = vv;
            if (tid < 64)
                Ms[tid] = pad_mask[b * S_LEN + kt * 64 + tid] * MASK_LOG2;
        }
        __syncthreads();

        // scores (already in log2 domain thanks to Q pre-scale)
        float sc[8][4];
        #pragma unroll
        for (int j = 0; j < 8; j++) {
            sc[j][0] = 0.f; sc[j][1] = 0.f; sc[j][2] = 0.f; sc[j][3] = 0.f;
            #pragma unroll
            for (int t = 0; t < 2; t++) {
                const uint32_t b0 = Ks[j * 8 + r][t * 8 + qq];
                const uint32_t b1 = Ks[j * 8 + r][t * 8 + qq + 4];
                mma_bf16(sc[j], qa[t][0], qa[t][1], qa[t][2], qa[t][3], b0, b1);
            }
        }

        // p = exp2(s + mask); accumulate per-lane sums; no max, no rescale
        #pragma unroll
        for (int j = 0; j < 8; j++) {
            const float2 mb = *reinterpret_cast<const float2*>(&Ms[j * 8 + qq * 2]);
            sc[j][0] = ex2f(sc[j][0] + mb.x);
            sc[j][1] = ex2f(sc[j][1] + mb.y);
            sc[j][2] = ex2f(sc[j][2] + mb.x);
            sc[j][3] = ex2f(sc[j][3] + mb.y);
            l0 += sc[j][0] + sc[j][1];
            l1 += sc[j][2] + sc[j][3];
        }

        // PV: O += P V  (P C-frags -> A-frags by pack, zero shuffles)
        #pragma unroll
        for (int jp = 0; jp < 4; jp++) {
            const uint32_t a0 = pack_bf16(sc[2 * jp    ][0], sc[2 * jp    ][1]);
            const uint32_t a1 = pack_bf16(sc[2 * jp    ][2], sc[2 * jp    ][3]);
            const uint32_t a2 = pack_bf16(sc[2 * jp + 1][0], sc[2 * jp + 1][1]);
            const uint32_t a3 = pack_bf16(sc[2 * jp + 1][2], sc[2 * jp + 1][3]);
            #pragma unroll
            for (int nn = 0; nn < 4; nn++) {
                const uint32_t b0 = Vs[nn * 8 + r][jp * 8 + qq];
                const uint32_t b1 = Vs[nn * 8 + r][jp * 8 + qq + 4];
                mma_bf16(oa[nn], a0, a1, a2, a3, b0, b1);
            }
        }
        __syncthreads();
    }

    // single end-of-kernel l reduction (quad covers the 64-col groups)
    l0 += __shfl_xor_sync(FULL_MASK, l0, 1);
    l0 += __shfl_xor_sync(FULL_MASK, l0, 2);
    l1 += __shfl_xor_sync(FULL_MASK, l1, 1);
    l1 += __shfl_xor_sync(FULL_MASK, l1, 2);
    const float i0 = 1.0f / l0;
    const float i1 = 1.0f / l1;

    float* Op = g_o + ((size_t)bh * S_LEN + q0) * DIM_HEAD;
    #pragma unroll
    for (int nn = 0; nn < 4; nn++) {
        *reinterpret_cast<float2*>(&Op[(r    ) * 32 + nn * 8 + qq * 2]) =
            make_float2(oa[nn][0] * i0, oa[nn][1] * i0);
        *reinterpret_cast<float2*>(&Op[(r + 8) * 32 + nn * 8 + qq * 2]) =
            make_float2(oa[nn][2] * i1, oa[nn][3] * i1);
    }
}

// ---------------------------------------------------------------------------
// Kernel 3: residual + LayerNorm. grid = B*S blocks, 256 threads.
// ---------------------------------------------------------------------------
__global__ void ln_kernel(const float* __restrict__ x,
                          const float* __restrict__ gamma,
                          const float* __restrict__ beta,
                          float* __restrict__ out) {
    const int row = blockIdx.x;
    const int d   = threadIdx.x;
    const int b   = row / S_LEN;
    const int s   = row - b * S_LEN;

    const float attn = g_o[(((size_t)(b * NUM_HEADS + (d >> 5))) * S_LEN + s) * DIM_HEAD + (d & 31)];
    const float val  = attn + x[(size_t)row * D_MODEL + d];

    float sum = val, sq = val * val;
    #pragma unroll
    for (int off = 16; off > 0; off >>= 1) {
        sum += __shfl_xor_sync(FULL_MASK, sum, off);
        sq  += __shfl_xor_sync(FULL_MASK, sq, off);
    }
    __shared__ float ra[8], rb[8];
    const int w = threadIdx.x >> 5, lane = threadIdx.x & 31;
    if (lane == 0) { ra[w] = sum; rb[w] = sq; }
    __syncthreads();
    if (threadIdx.x == 0) {
        float sa = 0.f, sb = 0.f;
        #pragma unroll
        for (int i = 0; i < 8; i++) { sa += ra[i]; sb += rb[i]; }
        ra[0] = sa; rb[0] = sb;
    }
    __syncthreads();
    const float mu  = ra[0] * (1.0f / D_MODEL);
    const float var = rb[0] * (1.0f / D_MODEL) - mu * mu;
    out[(size_t)row * D_MODEL + d] = gamma[d] * (val - mu) * rsqrtf(var + LN_EPS) + beta[d];
}

// ---------------------------------------------------------------------------
// Launch
// ---------------------------------------------------------------------------
extern "C" void kernel_launch(void* const* d_in, const int* in_sizes, int n_in,
                              void* d_out, int out_size) {
    const float* x     = (const float*)d_in[0];
    const float* pad   = (const float*)d_in[1];
    const float* Wq    = (const float*)d_in[2];
    const float* bq    = (const float*)d_in[3];
    const float* Wk    = (const float*)d_in[4];
    const float* bk    = (const float*)d_in[5];
    const float* Wv    = (const float*)d_in[6];
    const float* bv    = (const float*)d_in[7];
    const float* gamma = (const float*)d_in[8];
    const float* beta  = (const float*)d_in[9];

    const int N = in_sizes[1];           // pad_mask is [B,S] -> B*S rows
    const int B = N / S_LEN;

    qkv_mma_kernel<<<dim3(N / 128, 4, 3), 256>>>(x, Wq, bq, Wk, bk, Wv, bv);
    attn_mma_kernel<<<dim3(S_LEN / 128, NUM_HEADS, B), 256>>>(pad);
    ln_kernel<<<N, 256>>>(x, gamma, beta, (float*)d_out);
}

// round 5
// speedup vs baseline: 10.3729x; 1.0866x over previous
#include <cuda_runtime.h>
#include <cuda_bf16.h>
#include <math.h>
#include <stdint.h>

#define D_MODEL   256
#define NUM_HEADS 8
#define DIM_HEAD  32
#define S_LEN     4096
#define MAX_B     2
#define LN_EPS    1e-6f
#define FULL_MASK 0xffffffffu
#define QK_SCALE  0.2550565405694324f      // (1/sqrt(32)) * log2(e)
#define MASK_LOG2 (-2.550565405694324e8f)  // -1e9 * QK_SCALE

// bf16 scratch stored as packed words.
__device__ uint32_t g_q[MAX_B * NUM_HEADS * S_LEN * DIM_HEAD / 2];
__device__ uint32_t g_k[MAX_B * NUM_HEADS * S_LEN * DIM_HEAD / 2];
__device__ uint32_t g_v[MAX_B * NUM_HEADS * S_LEN * DIM_HEAD / 2];
__device__ float    g_o[MAX_B * NUM_HEADS * S_LEN * DIM_HEAD];

// ---------------------------------------------------------------------------
// Helpers
// ---------------------------------------------------------------------------
__device__ __forceinline__ uint32_t pack_bf16(float lo, float hi) {
    uint32_t r;
    asm("cvt.rn.bf16x2.f32 %0, %1, %2;" : "=r"(r) : "f"(hi), "f"(lo));
    return r;
}
__device__ __forceinline__ float ex2f(float x) {
    float y;
    asm("ex2.approx.f32 %0, %1;" : "=f"(y) : "f"(x));
    return y;
}
__device__ __forceinline__ void mma_bf16(float c[4],
                                         uint32_t a0, uint32_t a1, uint32_t a2, uint32_t a3,
                                         uint32_t b0, uint32_t b1) {
    asm volatile(
        "mma.sync.aligned.m16n8k16.row.col.f32.bf16.bf16.f32 "
        "{%0,%1,%2,%3},{%4,%5,%6,%7},{%8,%9},{%0,%1,%2,%3};"
        : "+f"(c[0]), "+f"(c[1]), "+f"(c[2]), "+f"(c[3])
        : "r"(a0), "r"(a1), "r"(a2), "r"(a3), "r"(b0), "r"(b1));
}
__device__ __forceinline__ void ldsm_x4(uint32_t& d0, uint32_t& d1,
                                        uint32_t& d2, uint32_t& d3, uint32_t addr) {
    asm volatile("ldmatrix.sync.aligned.m8n8.x4.shared.b16 {%0,%1,%2,%3}, [%4];"
                 : "=r"(d0), "=r"(d1), "=r"(d2), "=r"(d3) : "r"(addr));
}

// ---------------------------------------------------------------------------
// Kernel 1: QKV projection on tensor cores (bf16 mma, fp32 accum).
// grid = (rows/128, 4, 3), block = 256. (unchanged from R4)
// ---------------------------------------------------------------------------
__global__ void __launch_bounds__(256, 2)
qkv_mma_kernel(const float* __restrict__ x,
               const float* __restrict__ Wq, const float* __restrict__ bq,
               const float* __restrict__ Wk, const float* __restrict__ bk,
               const float* __restrict__ Wv, const float* __restrict__ bv) {
    __shared__ __align__(16) uint32_t As[128][36];
    __shared__ __align__(16) uint32_t Ws[64][36];

    const int z = blockIdx.z;
    const float* W;
    const float* bias;
    if (z == 0)      { W = Wq; bias = bq; }
    else if (z == 1) { W = Wk; bias = bk; }
    else             { W = Wv; bias = bv; }

    const int row0 = blockIdx.x * 128;
    const int n0   = blockIdx.y * 64;
    const int tid  = threadIdx.x;
    const int warp = tid >> 5, lane = tid & 31;
    const int r    = lane >> 2, qq = lane & 3;
    const int wm   = warp >> 1;
    const int wn   = warp & 1;

    float acc[2][4][4];
    #pragma unroll
    for (int mf = 0; mf < 2; mf++)
        #pragma unroll
        for (int nf = 0; nf < 4; nf++)
            #pragma unroll
            for (int i = 0; i < 4; i++) acc[mf][nf][i] = 0.f;

    for (int kc = 0; kc < 4; kc++) {
        const int k0 = kc * 64;
        #pragma unroll
        for (int w = 0; w < 8; w++) {
            const int idx = tid + w * 256;
            const int m = idx >> 4, ko = (idx & 15) * 4;
            const float4 f = *reinterpret_cast<const float4*>(
                &x[(size_t)(row0 + m) * D_MODEL + k0 + ko]);
            As[m][(ko >> 1)]     = pack_bf16(f.x, f.y);
            As[m][(ko >> 1) + 1] = pack_bf16(f.z, f.w);
        }
        #pragma unroll
        for (int i = 0; i < 2; i++) {
            const int g  = tid + i * 256;
            const int kw = g >> 4, n4 = (g & 15) * 4;
            const float4 f0 = *reinterpret_cast<const float4*>(
                &W[(size_t)(k0 + 2 * kw) * D_MODEL + n0 + n4]);
            const float4 f1 = *reinterpret_cast<const float4*>(
                &W[(size_t)(k0 + 2 * kw + 1) * D_MODEL + n0 + n4]);
            Ws[n4    ][kw] = pack_bf16(f0.x, f1.x);
            Ws[n4 + 1][kw] = pack_bf16(f0.y, f1.y);
            Ws[n4 + 2][kw] = pack_bf16(f0.z, f1.z);
            Ws[n4 + 3][kw] = pack_bf16(f0.w, f1.w);
        }
        __syncthreads();

        #pragma unroll
        for (int ks = 0; ks < 4; ks++) {
            uint32_t a[2][4], bf[4][2];
            #pragma unroll
            for (int mf = 0; mf < 2; mf++) {
                const int mr = wm * 32 + mf * 16;
                a[mf][0] = As[mr + r    ][ks * 8 + qq];
                a[mf][1] = As[mr + r + 8][ks * 8 + qq];
                a[mf][2] = As[mr + r    ][ks * 8 + qq + 4];
                a[mf][3] = As[mr + r + 8][ks * 8 + qq + 4];
            }
            #pragma unroll
            for (int nf = 0; nf < 4; nf++) {
                const int nr = wn * 32 + nf * 8;
                bf[nf][0] = Ws[nr + r][ks * 8 + qq];
                bf[nf][1] = Ws[nr + r][ks * 8 + qq + 4];
            }
            #pragma unroll
            for (int mf = 0; mf < 2; mf++)
                #pragma unroll
                for (int nf = 0; nf < 4; nf++)
                    mma_bf16(acc[mf][nf], a[mf][0], a[mf][1], a[mf][2], a[mf][3],
                             bf[nf][0], bf[nf][1]);
        }
        __syncthreads();
    }

    const int b  = row0 >> 12;
    const int s0 = row0 & (S_LEN - 1);

    if (z != 2) {
        uint32_t* out = (z == 0) ? g_q : g_k;
        const float scale = (z == 0) ? QK_SCALE : 1.0f;
        const int h  = (n0 >> 5) + wn;
        const int bh = b * NUM_HEADS + h;
        #pragma unroll
        for (int mf = 0; mf < 2; mf++) {
            const int s = s0 + wm * 32 + mf * 16;
            #pragma unroll
            for (int nf = 0; nf < 4; nf++) {
                const float2 bb = *reinterpret_cast<const float2*>(
                    &bias[n0 + wn * 32 + nf * 8 + qq * 2]);
                const float c0 = (acc[mf][nf][0] + bb.x) * scale;
                const float c1 = (acc[mf][nf][1] + bb.y) * scale;
                const float c2 = (acc[mf][nf][2] + bb.x) * scale;
                const float c3 = (acc[mf][nf][3] + bb.y) * scale;
                out[((size_t)bh * S_LEN + s + r    ) * 16 + nf * 4 + qq] = pack_bf16(c0, c1);
                out[((size_t)bh * S_LEN + s + r + 8) * 16 + nf * 4 + qq] = pack_bf16(c2, c3);
            }
        }
    } else {
        __nv_bfloat16* Vt = reinterpret_cast<__nv_bfloat16*>(&As[0][0]);
        #pragma unroll
        for (int mf = 0; mf < 2; mf++) {
            const int ml = wm * 32 + mf * 16;
            #pragma unroll
            for (int nf = 0; nf < 4; nf++) {
                const int nc = wn * 32 + nf * 8 + qq * 2;
                const float2 bb = *reinterpret_cast<const float2*>(&bias[n0 + nc]);
                Vt[(nc    ) * 136 + ml + r    ] = __float2bfloat16(acc[mf][nf][0] + bb.x);
                Vt[(nc + 1) * 136 + ml + r    ] = __float2bfloat16(acc[mf][nf][1] + bb.y);
                Vt[(nc    ) * 136 + ml + r + 8] = __float2bfloat16(acc[mf][nf][2] + bb.x);
                Vt[(nc + 1) * 136 + ml + r + 8] = __float2bfloat16(acc[mf][nf][3] + bb.y);
            }
        }
        __syncthreads();
        #pragma unroll
        for (int i = 0; i < 4; i++) {
            const int idx = tid + i * 256;
            const int n = idx >> 4, wq = (idx & 15) * 4;
            const uint4 val = *reinterpret_cast<const uint4*>(&Vt[n * 136 + wq * 2]);
            const int col = n0 + n;
            const int bh  = b * NUM_HEADS + (col >> 5);
            const int dh  = col & 31;
            *reinterpret_cast<uint4*>(
                &g_v[((size_t)bh * DIM_HEAD + dh) * (S_LEN / 2) + (s0 >> 1) + wq]) = val;
        }
    }
}

// ---------------------------------------------------------------------------
// Kernel 2: flash attention, bf16 mma, exp2-domain softmax (no running max),
// double-buffered smem tiles (1 barrier/tile), ldmatrix B-fragments.
// grid = (S/128, H, B), block = 256 (8 warps, 16 q-rows each). BK = 64.
// ---------------------------------------------------------------------------
__global__ void __launch_bounds__(256, 2)
attn_mma_kernel(const float* __restrict__ pad_mask) {
    __shared__ __align__(16) uint32_t Ks[2][64][20];
    __shared__ __align__(16) uint32_t Vs[2][32][36];
    __shared__ __align__(8)  float    Ms[2][64];

    const int tid  = threadIdx.x;
    const int warp = tid >> 5;
    const int lane = tid & 31;
    const int r    = lane >> 2;
    const int qq   = lane & 3;

    const int qt = blockIdx.x, h = blockIdx.y, b = blockIdx.z;
    const int bh = b * NUM_HEADS + h;
    const int q0 = qt * 128 + warp * 16;

    // ldmatrix per-lane base addresses (buffer 0)
    const uint32_t ks_base = (uint32_t)__cvta_generic_to_shared(
        &Ks[0][lane & 7][(lane >> 3) * 4]);
    const uint32_t vs_base = (uint32_t)__cvta_generic_to_shared(
        &Vs[0][lane & 7][(lane >> 3) * 4]);
    const uint32_t KS_BUF = 64 * 20 * 4;   // bytes per K buffer
    const uint32_t VS_BUF = 32 * 36 * 4;

    // Q fragments (Q pre-scaled by QK_SCALE in qkv kernel)
    uint32_t qa[2][4];
    {
        const uint32_t* Qw = g_q + ((size_t)bh * S_LEN + q0) * 16;
        #pragma unroll
        for (int t = 0; t < 2; t++) {
            qa[t][0] = Qw[(r    ) * 16 + t * 8 + qq    ];
            qa[t][1] = Qw[(r + 8) * 16 + t * 8 + qq    ];
            qa[t][2] = Qw[(r    ) * 16 + t * 8 + qq + 4];
            qa[t][3] = Qw[(r + 8) * 16 + t * 8 + qq + 4];
        }
    }

    float oa[4][4];
    #pragma unroll
    for (int nn = 0; nn < 4; nn++)
        #pragma unroll
        for (int i = 0; i < 4; i++) oa[nn][i] = 0.f;

    float l0 = 0.f, l1 = 0.f;

    const uint32_t* Kw = g_k + (size_t)bh * S_LEN * 16;
    const uint32_t* Vw = g_v + (size_t)bh * DIM_HEAD * (S_LEN / 2)
                       + (tid >> 3) * (S_LEN / 2) + (tid & 7) * 4;
    const float* Mp = pad_mask + b * S_LEN;

    // prologue: stage tile 0 into buffer 0
    uint4 kreg = *reinterpret_cast<const uint4*>(&Kw[tid * 4]);
    uint4 vreg = *reinterpret_cast<const uint4*>(Vw);
    float mreg = (tid < 64) ? Mp[tid] * MASK_LOG2 : 0.f;
    *reinterpret_cast<uint4*>(&Ks[0][tid >> 2][(tid & 3) * 4]) = kreg;
    *reinterpret_cast<uint4*>(&Vs[0][tid >> 3][(tid & 7) * 4]) = vreg;
    if (tid < 64) Ms[0][tid] = mreg;
    __syncthreads();

    int p = 0;
    for (int kt = 0; kt < S_LEN / 64; kt++) {
        // issue next tile's global loads early (latency hidden under compute)
        if (kt + 1 < S_LEN / 64) {
            kreg = *reinterpret_cast<const uint4*>(&Kw[(kt + 1) * 1024 + tid * 4]);
            vreg = *reinterpret_cast<const uint4*>(Vw + (kt + 1) * 32);
            if (tid < 64) mreg = Mp[(kt + 1) * 64 + tid] * MASK_LOG2;
        }

        const uint32_t kaddr = ks_base + (uint32_t)p * KS_BUF;
        const uint32_t vaddr = vs_base + (uint32_t)p * VS_BUF;

        // ---- scores: 8 ldmatrix.x4 + 16 mma ----
        float sc[8][4];
        #pragma unroll
        for (int j = 0; j < 8; j++) {
            uint32_t b00, b01, b10, b11;
            ldsm_x4(b00, b01, b10, b11, kaddr + j * (8 * 20 * 4));
            sc[j][0] = 0.f; sc[j][1] = 0.f; sc[j][2] = 0.f; sc[j][3] = 0.f;
            mma_bf16(sc[j], qa[0][0], qa[0][1], qa[0][2], qa[0][3], b00, b01);
            mma_bf16(sc[j], qa[1][0], qa[1][1], qa[1][2], qa[1][3], b10, b11);
        }

        // ---- p = exp2(s + mask); accumulate row sums ----
        #pragma unroll
        for (int j = 0; j < 8; j++) {
            const float2 mb = *reinterpret_cast<const float2*>(&Ms[p][j * 8 + qq * 2]);
            sc[j][0] = ex2f(sc[j][0] + mb.x);
            sc[j][1] = ex2f(sc[j][1] + mb.y);
            sc[j][2] = ex2f(sc[j][2] + mb.x);
            sc[j][3] = ex2f(sc[j][3] + mb.y);
            l0 += sc[j][0] + sc[j][1];
            l1 += sc[j][2] + sc[j][3];
        }

        // ---- pack P into A-fragments ----
        uint32_t pa[4][4];
        #pragma unroll
        for (int jp = 0; jp < 4; jp++) {
            pa[jp][0] = pack_bf16(sc[2 * jp    ][0], sc[2 * jp    ][1]);
            pa[jp][1] = pack_bf16(sc[2 * jp    ][2], sc[2 * jp    ][3]);
            pa[jp][2] = pack_bf16(sc[2 * jp + 1][0], sc[2 * jp + 1][1]);
            pa[jp][3] = pack_bf16(sc[2 * jp + 1][2], sc[2 * jp + 1][3]);
        }

        // ---- PV: 8 ldmatrix.x4 + 16 mma ----
        #pragma unroll
        for (int nn = 0; nn < 4; nn++) {
            uint32_t vb[4][2];
            ldsm_x4(vb[0][0], vb[0][1], vb[1][0], vb[1][1],
                    vaddr + nn * (8 * 36 * 4));
            ldsm_x4(vb[2][0], vb[2][1], vb[3][0], vb[3][1],
                    vaddr + nn * (8 * 36 * 4) + 64);
            #pragma unroll
            for (int jp = 0; jp < 4; jp++)
                mma_bf16(oa[nn], pa[jp][0], pa[jp][1], pa[jp][2], pa[jp][3],
                         vb[jp][0], vb[jp][1]);
        }

        // ---- store staged regs into the other buffer; single barrier ----
        if (kt + 1 < S_LEN / 64) {
            const int np = p ^ 1;
            *reinterpret_cast<uint4*>(&Ks[np][tid >> 2][(tid & 3) * 4]) = kreg;
            *reinterpret_cast<uint4*>(&Vs[np][tid >> 3][(tid & 7) * 4]) = vreg;
            if (tid < 64) Ms[np][tid] = mreg;
            __syncthreads();
        }
        p ^= 1;
    }

    // final l reduction within quads (each quad spans the 64 key columns)
    l0 += __shfl_xor_sync(FULL_MASK, l0, 1);
    l0 += __shfl_xor_sync(FULL_MASK, l0, 2);
    l1 += __shfl_xor_sync(FULL_MASK, l1, 1);
    l1 += __shfl_xor_sync(FULL_MASK, l1, 2);
    const float i0 = 1.0f / l0;
    const float i1 = 1.0f / l1;

    float* Op = g_o + ((size_t)bh * S_LEN + q0) * DIM_HEAD;
    #pragma unroll
    for (int nn = 0; nn < 4; nn++) {
        *reinterpret_cast<float2*>(&Op[(r    ) * 32 + nn * 8 + qq * 2]) =
            make_float2(oa[nn][0] * i0, oa[nn][1] * i0);
        *reinterpret_cast<float2*>(&Op[(r + 8) * 32 + nn * 8 + qq * 2]) =
            make_float2(oa[nn][2] * i1, oa[nn][3] * i1);
    }
}

// ---------------------------------------------------------------------------
// Kernel 3: residual + LayerNorm, warp-per-row (no block barriers).
// grid = N/8 blocks, 256 threads = 8 warps, 1 row per warp.
// ---------------------------------------------------------------------------
__global__ void ln_kernel(const float* __restrict__ x,
                          const float* __restrict__ gamma,
                          const float* __restrict__ beta,
                          float* __restrict__ out) {
    const int warp = threadIdx.x >> 5;
    const int lane = threadIdx.x & 31;
    const int row  = blockIdx.x * 8 + warp;      // b*S + s
    const int b    = row >> 12;                  // S_LEN = 4096
    const int s    = row & (S_LEN - 1);

    const int d0 = lane * 8;                     // 8 dims per lane, head-aligned
    const int bh = b * NUM_HEADS + (d0 >> 5);
    const float* Oq = &g_o[((size_t)bh * S_LEN + s) * DIM_HEAD + (d0 & 31)];
    const float* Xq = &x[(size_t)row * D_MODEL + d0];

    float v[8];
    {
        const float4 a0 = *reinterpret_cast<const float4*>(Oq);
        const float4 a1 = *reinterpret_cast<const float4*>(Oq + 4);
        const float4 x0 = *reinterpret_cast<const float4*>(Xq);
        const float4 x1 = *reinterpret_cast<const float4*>(Xq + 4);
        v[0] = a0.x + x0.x; v[1] = a0.y + x0.y; v[2] = a0.z + x0.z; v[3] = a0.w + x0.w;
        v[4] = a1.x + x1.x; v[5] = a1.y + x1.y; v[6] = a1.z + x1.z; v[7] = a1.w + x1.w;
    }

    float sum = 0.f, sq = 0.f;
    #pragma unroll
    for (int i = 0; i < 8; i++) { sum += v[i]; sq += v[i] * v[i]; }
    #pragma unroll
    for (int off = 16; off > 0; off >>= 1) {
        sum += __shfl_xor_sync(FULL_MASK, sum, off);
        sq  += __shfl_xor_sync(FULL_MASK, sq,  off);
    }
    const float mu  = sum * (1.0f / D_MODEL);
    const float var = sq * (1.0f / D_MODEL) - mu * mu;
    const float rs  = rsqrtf(var + LN_EPS);

    const float4 g0 = *reinterpret_cast<const float4*>(&gamma[d0]);
    const float4 g1 = *reinterpret_cast<const float4*>(&gamma[d0 + 4]);
    const float4 b0 = *reinterpret_cast<const float4*>(&beta[d0]);
    const float4 b1 = *reinterpret_cast<const float4*>(&beta[d0 + 4]);

    float4 o0, o1;
    o0.x = g0.x * (v[0] - mu) * rs + b0.x;
    o0.y = g0.y * (v[1] - mu) * rs + b0.y;
    o0.z = g0.z * (v[2] - mu) * rs + b0.z;
    o0.w = g0.w * (v[3] - mu) * rs + b0.w;
    o1.x = g1.x * (v[4] - mu) * rs + b1.x;
    o1.y = g1.y * (v[5] - mu) * rs + b1.y;
    o1.z = g1.z * (v[6] - mu) * rs + b1.z;
    o1.w = g1.w * (v[7] - mu) * rs + b1.w;
    *reinterpret_cast<float4*>(&out[(size_t)row * D_MODEL + d0])     = o0;
    *reinterpret_cast<float4*>(&out[(size_t)row * D_MODEL + d0 + 4]) = o1;
}

// ---------------------------------------------------------------------------
// Launch
// ---------------------------------------------------------------------------
extern "C" void kernel_launch(void* const* d_in, const int* in_sizes, int n_in,
                              void* d_out, int out_size) {
    const float* x     = (const float*)d_in[0];
    const float* pad   = (const float*)d_in[1];
    const float* Wq    = (const float*)d_in[2];
    const float* bq    = (const float*)d_in[3];
    const float* Wk    = (const float*)d_in[4];
    const float* bk    = (const float*)d_in[5];
    const float* Wv    = (const float*)d_in[6];
    const float* bv    = (const float*)d_in[7];
    const float* gamma = (const float*)d_in[8];
    const float* beta  = (const float*)d_in[9];

    const int N = in_sizes[1];           // pad_mask is [B,S] -> B*S rows
    const int B = N / S_LEN;

    qkv_mma_kernel<<<dim3(N / 128, 4, 3), 256>>>(x, Wq, bq, Wk, bk, Wv, bv);
    attn_mma_kernel<<<dim3(S_LEN / 128, NUM_HEADS, B), 256>>>(pad);
    ln_kernel<<<N / 8, 256>>>(x, gamma, beta, (float*)d_out);
}

// round 6
// speedup vs baseline: 11.1595x; 1.0758x over previous
#include <cuda_runtime.h>
#include <cuda_fp16.h>
#include <math.h>
#include <stdint.h>

#define D_MODEL   256
#define NUM_HEADS 8
#define DIM_HEAD  32
#define S_LEN     4096
#define MAX_B     2
#define LN_EPS    1e-6f
#define FULL_MASK 0xffffffffu
#define QK_SCALE  0.2550565405694324f      // (1/sqrt(32)) * log2(e)
#define MASK_LOG2 (-2.550565405694324e8f)  // -1e9 * QK_SCALE

// f16 scratch stored as packed words.
__device__ uint32_t g_q[MAX_B * NUM_HEADS * S_LEN * DIM_HEAD / 2];
__device__ uint32_t g_k[MAX_B * NUM_HEADS * S_LEN * DIM_HEAD / 2];
__device__ uint32_t g_v[MAX_B * NUM_HEADS * S_LEN * DIM_HEAD / 2];
__device__ float    g_o[MAX_B * NUM_HEADS * S_LEN * DIM_HEAD];

// ---------------------------------------------------------------------------
// Helpers
// ---------------------------------------------------------------------------
__device__ __forceinline__ uint32_t pack_f16(float lo, float hi) {
    uint32_t r;
    asm("cvt.rn.f16x2.f32 %0, %1, %2;" : "=r"(r) : "f"(hi), "f"(lo));
    return r;
}
__device__ __forceinline__ uint32_t ex2_f16x2(uint32_t x) {
    uint32_t y;
    asm("ex2.approx.f16x2 %0, %1;" : "=r"(y) : "r"(x));
    return y;
}
__device__ __forceinline__ void mma_f16(float c[4],
                                        uint32_t a0, uint32_t a1, uint32_t a2, uint32_t a3,
                                        uint32_t b0, uint32_t b1) {
    asm volatile(
        "mma.sync.aligned.m16n8k16.row.col.f32.f16.f16.f32 "
        "{%0,%1,%2,%3},{%4,%5,%6,%7},{%8,%9},{%0,%1,%2,%3};"
        : "+f"(c[0]), "+f"(c[1]), "+f"(c[2]), "+f"(c[3])
        : "r"(a0), "r"(a1), "r"(a2), "r"(a3), "r"(b0), "r"(b1));
}
__device__ __forceinline__ void ldsm_x4(uint32_t& d0, uint32_t& d1,
                                        uint32_t& d2, uint32_t& d3, uint32_t addr) {
    asm volatile("ldmatrix.sync.aligned.m8n8.x4.shared.b16 {%0,%1,%2,%3}, [%4];"
                 : "=r"(d0), "=r"(d1), "=r"(d2), "=r"(d3) : "r"(addr));
}

// ---------------------------------------------------------------------------
// Kernel 1: QKV projection on tensor cores (f16 mma, fp32 accum).
// grid = (rows/128, 4, 3), block = 256 (8 warps: 4 m-quarters x 2 n-halves).
// ---------------------------------------------------------------------------
__global__ void __launch_bounds__(256, 2)
qkv_mma_kernel(const float* __restrict__ x,
               const float* __restrict__ Wq, const float* __restrict__ bq,
               const float* __restrict__ Wk, const float* __restrict__ bk,
               const float* __restrict__ Wv, const float* __restrict__ bv) {
    __shared__ __align__(16) uint32_t As[128][36];
    __shared__ __align__(16) uint32_t Ws[64][36];

    const int z = blockIdx.z;
    const float* W;
    const float* bias;
    if (z == 0)      { W = Wq; bias = bq; }
    else if (z == 1) { W = Wk; bias = bk; }
    else             { W = Wv; bias = bv; }

    const int row0 = blockIdx.x * 128;
    const int n0   = blockIdx.y * 64;
    const int tid  = threadIdx.x;
    const int warp = tid >> 5, lane = tid & 31;
    const int r    = lane >> 2, qq = lane & 3;
    const int wm   = warp >> 1;
    const int wn   = warp & 1;

    float acc[2][4][4];
    #pragma unroll
    for (int mf = 0; mf < 2; mf++)
        #pragma unroll
        for (int nf = 0; nf < 4; nf++)
            #pragma unroll
            for (int i = 0; i < 4; i++) acc[mf][nf][i] = 0.f;

    for (int kc = 0; kc < 4; kc++) {
        const int k0 = kc * 64;
        #pragma unroll
        for (int w = 0; w < 8; w++) {
            const int idx = tid + w * 256;
            const int m = idx >> 4, ko = (idx & 15) * 4;
            const float4 f = *reinterpret_cast<const float4*>(
                &x[(size_t)(row0 + m) * D_MODEL + k0 + ko]);
            As[m][(ko >> 1)]     = pack_f16(f.x, f.y);
            As[m][(ko >> 1) + 1] = pack_f16(f.z, f.w);
        }
        #pragma unroll
        for (int i = 0; i < 2; i++) {
            const int g  = tid + i * 256;
            const int kw = g >> 4, n4 = (g & 15) * 4;
            const float4 f0 = *reinterpret_cast<const float4*>(
                &W[(size_t)(k0 + 2 * kw) * D_MODEL + n0 + n4]);
            const float4 f1 = *reinterpret_cast<const float4*>(
                &W[(size_t)(k0 + 2 * kw + 1) * D_MODEL + n0 + n4]);
            Ws[n4    ][kw] = pack_f16(f0.x, f1.x);
            Ws[n4 + 1][kw] = pack_f16(f0.y, f1.y);
            Ws[n4 + 2][kw] = pack_f16(f0.z, f1.z);
            Ws[n4 + 3][kw] = pack_f16(f0.w, f1.w);
        }
        __syncthreads();

        #pragma unroll
        for (int ks = 0; ks < 4; ks++) {
            uint32_t a[2][4], bf[4][2];
            #pragma unroll
            for (int mf = 0; mf < 2; mf++) {
                const int mr = wm * 32 + mf * 16;
                a[mf][0] = As[mr + r    ][ks * 8 + qq];
                a[mf][1] = As[mr + r + 8][ks * 8 + qq];
                a[mf][2] = As[mr + r    ][ks * 8 + qq + 4];
                a[mf][3] = As[mr + r + 8][ks * 8 + qq + 4];
            }
            #pragma unroll
            for (int nf = 0; nf < 4; nf++) {
                const int nr = wn * 32 + nf * 8;
                bf[nf][0] = Ws[nr + r][ks * 8 + qq];
                bf[nf][1] = Ws[nr + r][ks * 8 + qq + 4];
            }
            #pragma unroll
            for (int mf = 0; mf < 2; mf++)
                #pragma unroll
                for (int nf = 0; nf < 4; nf++)
                    mma_f16(acc[mf][nf], a[mf][0], a[mf][1], a[mf][2], a[mf][3],
                            bf[nf][0], bf[nf][1]);
        }
        __syncthreads();
    }

    const int b  = row0 >> 12;
    const int s0 = row0 & (S_LEN - 1);

    if (z != 2) {
        uint32_t* out = (z == 0) ? g_q : g_k;
        const float scale = (z == 0) ? QK_SCALE : 1.0f;
        const int h  = (n0 >> 5) + wn;
        const int bh = b * NUM_HEADS + h;
        #pragma unroll
        for (int mf = 0; mf < 2; mf++) {
            const int s = s0 + wm * 32 + mf * 16;
            #pragma unroll
            for (int nf = 0; nf < 4; nf++) {
                const float2 bb = *reinterpret_cast<const float2*>(
                    &bias[n0 + wn * 32 + nf * 8 + qq * 2]);
                const float c0 = (acc[mf][nf][0] + bb.x) * scale;
                const float c1 = (acc[mf][nf][1] + bb.y) * scale;
                const float c2 = (acc[mf][nf][2] + bb.x) * scale;
                const float c3 = (acc[mf][nf][3] + bb.y) * scale;
                out[((size_t)bh * S_LEN + s + r    ) * 16 + nf * 4 + qq] = pack_f16(c0, c1);
                out[((size_t)bh * S_LEN + s + r + 8) * 16 + nf * 4 + qq] = pack_f16(c2, c3);
            }
        }
    } else {
        __half* Vt = reinterpret_cast<__half*>(&As[0][0]);
        #pragma unroll
        for (int mf = 0; mf < 2; mf++) {
            const int ml = wm * 32 + mf * 16;
            #pragma unroll
            for (int nf = 0; nf < 4; nf++) {
                const int nc = wn * 32 + nf * 8 + qq * 2;
                const float2 bb = *reinterpret_cast<const float2*>(&bias[n0 + nc]);
                Vt[(nc    ) * 136 + ml + r    ] = __float2half(acc[mf][nf][0] + bb.x);
                Vt[(nc + 1) * 136 + ml + r    ] = __float2half(acc[mf][nf][1] + bb.y);
                Vt[(nc    ) * 136 + ml + r + 8] = __float2half(acc[mf][nf][2] + bb.x);
                Vt[(nc + 1) * 136 + ml + r + 8] = __float2half(acc[mf][nf][3] + bb.y);
            }
        }
        __syncthreads();
        #pragma unroll
        for (int i = 0; i < 4; i++) {
            const int idx = tid + i * 256;
            const int n = idx >> 4, wq = (idx & 15) * 4;
            const uint4 val = *reinterpret_cast<const uint4*>(&Vt[n * 136 + wq * 2]);
            const int col = n0 + n;
            const int bh  = b * NUM_HEADS + (col >> 5);
            const int dh  = col & 31;
            *reinterpret_cast<uint4*>(
                &g_v[((size_t)bh * DIM_HEAD + dh) * (S_LEN / 2) + (s0 >> 1) + wq]) = val;
        }
    }
}

// ---------------------------------------------------------------------------
// Kernel 2: flash attention, f16 mma, f16x2 exp2, l via ones-column mma.
// grid = (S/128, H, B), block = 256 (8 warps, 16 q-rows each). BK = 64.
// ---------------------------------------------------------------------------
__global__ void __launch_bounds__(256, 2)
attn_mma_kernel(const float* __restrict__ pad_mask) {
    __shared__ __align__(16) uint32_t Ks[2][64][20];
    __shared__ __align__(16) uint32_t Vs[2][32][36];
    __shared__ __align__(8)  float    Ms[2][64];

    const int tid  = threadIdx.x;
    const int warp = tid >> 5;
    const int lane = tid & 31;
    const int r    = lane >> 2;
    const int qq   = lane & 3;

    const int qt = blockIdx.x, h = blockIdx.y, b = blockIdx.z;
    const int bh = b * NUM_HEADS + h;
    const int q0 = qt * 128 + warp * 16;

    const uint32_t ks_base = (uint32_t)__cvta_generic_to_shared(
        &Ks[0][lane & 7][(lane >> 3) * 4]);
    const uint32_t vs_base = (uint32_t)__cvta_generic_to_shared(
        &Vs[0][lane & 7][(lane >> 3) * 4]);
    const uint32_t KS_BUF = 64 * 20 * 4;
    const uint32_t VS_BUF = 32 * 36 * 4;
    const uint32_t ONES   = 0x3C003C00u;   // f16 (1.0, 1.0)

    // Q fragments (pre-scaled by QK_SCALE)
    uint32_t qa[2][4];
    {
        const uint32_t* Qw = g_q + ((size_t)bh * S_LEN + q0) * 16;
        #pragma unroll
        for (int t = 0; t < 2; t++) {
            qa[t][0] = Qw[(r    ) * 16 + t * 8 + qq    ];
            qa[t][1] = Qw[(r + 8) * 16 + t * 8 + qq    ];
            qa[t][2] = Qw[(r    ) * 16 + t * 8 + qq + 4];
            qa[t][3] = Qw[(r + 8) * 16 + t * 8 + qq + 4];
        }
    }

    float oa[4][4];
    #pragma unroll
    for (int nn = 0; nn < 4; nn++)
        #pragma unroll
        for (int i = 0; i < 4; i++) oa[nn][i] = 0.f;
    float oL[4] = {0.f, 0.f, 0.f, 0.f};   // row-sum accumulator (ones column)

    const uint32_t* Kw = g_k + (size_t)bh * S_LEN * 16;
    const uint32_t* Vw = g_v + (size_t)bh * DIM_HEAD * (S_LEN / 2)
                       + (tid >> 3) * (S_LEN / 2) + (tid & 7) * 4;
    const float* Mp = pad_mask + b * S_LEN;

    uint4 kreg = *reinterpret_cast<const uint4*>(&Kw[tid * 4]);
    uint4 vreg = *reinterpret_cast<const uint4*>(Vw);
    float mreg = (tid < 64) ? Mp[tid] * MASK_LOG2 : 0.f;
    *reinterpret_cast<uint4*>(&Ks[0][tid >> 2][(tid & 3) * 4]) = kreg;
    *reinterpret_cast<uint4*>(&Vs[0][tid >> 3][(tid & 7) * 4]) = vreg;
    if (tid < 64) Ms[0][tid] = mreg;
    __syncthreads();

    int p = 0;
    for (int kt = 0; kt < S_LEN / 64; kt++) {
        if (kt + 1 < S_LEN / 64) {
            kreg = *reinterpret_cast<const uint4*>(&Kw[(kt + 1) * 1024 + tid * 4]);
            vreg = *reinterpret_cast<const uint4*>(Vw + (kt + 1) * 32);
            if (tid < 64) mreg = Mp[(kt + 1) * 64 + tid] * MASK_LOG2;
        }

        const uint32_t kaddr = ks_base + (uint32_t)p * KS_BUF;
        const uint32_t vaddr = vs_base + (uint32_t)p * VS_BUF;

        // ---- scores ----
        float sc[8][4];
        #pragma unroll
        for (int j = 0; j < 8; j++) {
            uint32_t b00, b01, b10, b11;
            ldsm_x4(b00, b01, b10, b11, kaddr + j * (8 * 20 * 4));
            sc[j][0] = 0.f; sc[j][1] = 0.f; sc[j][2] = 0.f; sc[j][3] = 0.f;
            mma_f16(sc[j], qa[0][0], qa[0][1], qa[0][2], qa[0][3], b00, b01);
            mma_f16(sc[j], qa[1][0], qa[1][1], qa[1][2], qa[1][3], b10, b11);
        }

        // ---- p = exp2(s + mask), f16x2 MUFU; output IS the PV A-fragment ----
        uint32_t pa[4][4];
        #pragma unroll
        for (int j = 0; j < 8; j++) {
            const float2 mb = *reinterpret_cast<const float2*>(&Ms[p][j * 8 + qq * 2]);
            const uint32_t u01 = pack_f16(sc[j][0] + mb.x, sc[j][1] + mb.y);
            const uint32_t u23 = pack_f16(sc[j][2] + mb.x, sc[j][3] + mb.y);
            pa[j >> 1][(j & 1) * 2    ] = ex2_f16x2(u01);
            pa[j >> 1][(j & 1) * 2 + 1] = ex2_f16x2(u23);
        }

        // ---- PV (+ ones column accumulating row sums in fp32) ----
        #pragma unroll
        for (int nn = 0; nn < 4; nn++) {
            uint32_t vb[4][2];
            ldsm_x4(vb[0][0], vb[0][1], vb[1][0], vb[1][1],
                    vaddr + nn * (8 * 36 * 4));
            ldsm_x4(vb[2][0], vb[2][1], vb[3][0], vb[3][1],
                    vaddr + nn * (8 * 36 * 4) + 64);
            #pragma unroll
            for (int jp = 0; jp < 4; jp++)
                mma_f16(oa[nn], pa[jp][0], pa[jp][1], pa[jp][2], pa[jp][3],
                        vb[jp][0], vb[jp][1]);
        }
        #pragma unroll
        for (int jp = 0; jp < 4; jp++)
            mma_f16(oL, pa[jp][0], pa[jp][1], pa[jp][2], pa[jp][3], ONES, ONES);

        if (kt + 1 < S_LEN / 64) {
            const int np = p ^ 1;
            *reinterpret_cast<uint4*>(&Ks[np][tid >> 2][(tid & 3) * 4]) = kreg;
            *reinterpret_cast<uint4*>(&Vs[np][tid >> 3][(tid & 7) * 4]) = vreg;
            if (tid < 64) Ms[np][tid] = mreg;
            __syncthreads();
        }
        p ^= 1;
    }

    // l comes straight out of the ones-column C-fragment (rows r, r+8)
    const float i0 = 1.0f / oL[0];
    const float i1 = 1.0f / oL[2];

    float* Op = g_o + ((size_t)bh * S_LEN + q0) * DIM_HEAD;
    #pragma unroll
    for (int nn = 0; nn < 4; nn++) {
        *reinterpret_cast<float2*>(&Op[(r    ) * 32 + nn * 8 + qq * 2]) =
            make_float2(oa[nn][0] * i0, oa[nn][1] * i0);
        *reinterpret_cast<float2*>(&Op[(r + 8) * 32 + nn * 8 + qq * 2]) =
            make_float2(oa[nn][2] * i1, oa[nn][3] * i1);
    }
}

// ---------------------------------------------------------------------------
// Kernel 3: residual + LayerNorm, warp-per-row.
// ---------------------------------------------------------------------------
__global__ void ln_kernel(const float* __restrict__ x,
                          const float* __restrict__ gamma,
                          const float* __restrict__ beta,
                          float* __restrict__ out) {
    const int warp = threadIdx.x >> 5;
    const int lane = threadIdx.x & 31;
    const int row  = blockIdx.x * 8 + warp;
    const int b    = row >> 12;
    const int s    = row & (S_LEN - 1);

    const int d0 = lane * 8;
    const int bh = b * NUM_HEADS + (d0 >> 5);
    const float* Oq = &g_o[((size_t)bh * S_LEN + s) * DIM_HEAD + (d0 & 31)];
    const float* Xq = &x[(size_t)row * D_MODEL + d0];

    float v[8];
    {
        const float4 a0 = *reinterpret_cast<const float4*>(Oq);
        const float4 a1 = *reinterpret_cast<const float4*>(Oq + 4);
        const float4 x0 = *reinterpret_cast<const float4*>(Xq);
        const float4 x1 = *reinterpret_cast<const float4*>(Xq + 4);
        v[0] = a0.x + x0.x; v[1] = a0.y + x0.y; v[2] = a0.z + x0.z; v[3] = a0.w + x0.w;
        v[4] = a1.x + x1.x; v[5] = a1.y + x1.y; v[6] = a1.z + x1.z; v[7] = a1.w + x1.w;
    }

    float sum = 0.f, sq = 0.f;
    #pragma unroll
    for (int i = 0; i < 8; i++) { sum += v[i]; sq += v[i] * v[i]; }
    #pragma unroll
    for (int off = 16; off > 0; off >>= 1) {
        sum += __shfl_xor_sync(FULL_MASK, sum, off);
        sq  += __shfl_xor_sync(FULL_MASK, sq,  off);
    }
    const float mu  = sum * (1.0f / D_MODEL);
    const float var = sq * (1.0f / D_MODEL) - mu * mu;
    const float rs  = rsqrtf(var + LN_EPS);

    const float4 g0 = *reinterpret_cast<const float4*>(&gamma[d0]);
    const float4 g1 = *reinterpret_cast<const float4*>(&gamma[d0 + 4]);
    const float4 b0 = *reinterpret_cast<const float4*>(&beta[d0]);
    const float4 b1 = *reinterpret_cast<const float4*>(&beta[d0 + 4]);

    float4 o0, o1;
    o0.x = g0.x * (v[0] - mu) * rs + b0.x;
    o0.y = g0.y * (v[1] - mu) * rs + b0.y;
    o0.z = g0.z * (v[2] - mu) * rs + b0.z;
    o0.w = g0.w * (v[3] - mu) * rs + b0.w;
    o1.x = g1.x * (v[4] - mu) * rs + b1.x;
    o1.y = g1.y * (v[5] - mu) * rs + b1.y;
    o1.z = g1.z * (v[6] - mu) * rs + b1.z;
    o1.w = g1.w * (v[7] - mu) * rs + b1.w;
    *reinterpret_cast<float4*>(&out[(size_t)row * D_MODEL + d0])     = o0;
    *reinterpret_cast<float4*>(&out[(size_t)row * D_MODEL + d0 + 4]) = o1;
}

// ---------------------------------------------------------------------------
// Launch
// ---------------------------------------------------------------------------
extern "C" void kernel_launch(void* const* d_in, const int* in_sizes, int n_in,
                              void* d_out, int out_size) {
    const float* x     = (const float*)d_in[0];
    const float* pad   = (const float*)d_in[1];
    const float* Wq    = (const float*)d_in[2];
    const float* bq    = (const float*)d_in[3];
    const float* Wk    = (const float*)d_in[4];
    const float* bk    = (const float*)d_in[5];
    const float* Wv    = (const float*)d_in[6];
    const float* bv    = (const float*)d_in[7];
    const float* gamma = (const float*)d_in[8];
    const float* beta  = (const float*)d_in[9];

    const int N = in_sizes[1];
    const int B = N / S_LEN;

    qkv_mma_kernel<<<dim3(N / 128, 4, 3), 256>>>(x, Wq, bq, Wk, bk, Wv, bv);
    attn_mma_kernel<<<dim3(S_LEN / 128, NUM_HEADS, B), 256>>>(pad);
    ln_kernel<<<N / 8, 256>>>(x, gamma, beta, (float*)d_out);
}

// round 7
// speedup vs baseline: 12.3630x; 1.1079x over previous
#include <cuda_runtime.h>
#include <cuda_fp16.h>
#include <math.h>
#include <stdint.h>

#define D_MODEL   256
#define NUM_HEADS 8
#define DIM_HEAD  32
#define S_LEN     4096
#define MAX_B     2
#define LN_EPS    1e-6f
#define FULL_MASK 0xffffffffu
#define QK_SCALE  0.2550565405694324f      // (1/sqrt(32)) * log2(e)
#define MASK_LOG2 (-2.550565405694324e8f)  // -1e9 * QK_SCALE

// f16 scratch stored as packed words.
__device__ uint32_t g_xh[MAX_B * S_LEN * D_MODEL / 2];        // [N][128w] f16 x
__device__ uint32_t g_wt[3 * D_MODEL * D_MODEL / 2];          // [z][n][128w] f16 W^T
__device__ uint32_t g_q[MAX_B * NUM_HEADS * S_LEN * DIM_HEAD / 2];
__device__ uint32_t g_k[MAX_B * NUM_HEADS * S_LEN * DIM_HEAD / 2];
__device__ uint32_t g_v[MAX_B * NUM_HEADS * S_LEN * DIM_HEAD / 2];
__device__ float    g_o[MAX_B * NUM_HEADS * S_LEN * DIM_HEAD];

// ---------------------------------------------------------------------------
// Helpers
// ---------------------------------------------------------------------------
__device__ __forceinline__ uint32_t pack_f16(float lo, float hi) {
    uint32_t r;
    asm("cvt.rn.f16x2.f32 %0, %1, %2;" : "=r"(r) : "f"(hi), "f"(lo));
    return r;
}
__device__ __forceinline__ uint32_t ex2_f16x2(uint32_t x) {
    uint32_t y;
    asm("ex2.approx.f16x2 %0, %1;" : "=r"(y) : "r"(x));
    return y;
}
__device__ __forceinline__ void mma_f16(float c[4],
                                        uint32_t a0, uint32_t a1, uint32_t a2, uint32_t a3,
                                        uint32_t b0, uint32_t b1) {
    asm volatile(
        "mma.sync.aligned.m16n8k16.row.col.f32.f16.f16.f32 "
        "{%0,%1,%2,%3},{%4,%5,%6,%7},{%8,%9},{%0,%1,%2,%3};"
        : "+f"(c[0]), "+f"(c[1]), "+f"(c[2]), "+f"(c[3])
        : "r"(a0), "r"(a1), "r"(a2), "r"(a3), "r"(b0), "r"(b1));
}
__device__ __forceinline__ void ldsm_x4(uint32_t& d0, uint32_t& d1,
                                        uint32_t& d2, uint32_t& d3, uint32_t addr) {
    asm volatile("ldmatrix.sync.aligned.m8n8.x4.shared.b16 {%0,%1,%2,%3}, [%4];"
                 : "=r"(d0), "=r"(d1), "=r"(d2), "=r"(d3) : "r"(addr));
}
__device__ __forceinline__ void cp16(uint32_t dst, const void* src) {
    asm volatile("cp.async.cg.shared.global [%0], [%1], 16;" :: "r"(dst), "l"(src));
}
__device__ __forceinline__ void cp4(uint32_t dst, const void* src) {
    asm volatile("cp.async.ca.shared.global [%0], [%1], 4;" :: "r"(dst), "l"(src));
}
__device__ __forceinline__ void cp_commit() {
    asm volatile("cp.async.commit_group;");
}
__device__ __forceinline__ void cp_wait0() {
    asm volatile("cp.async.wait_group 0;");
}
__device__ __forceinline__ void cp_wait1() {
    asm volatile("cp.async.wait_group 1;");
}

// ---------------------------------------------------------------------------
// Kernel 0: fp32 -> f16 conversion. x -> g_xh; W (transposed) -> g_wt.
// grid = (xblocks + 384), block 256.
// ---------------------------------------------------------------------------
__global__ void convert_kernel(const float* __restrict__ x,
                               const float* __restrict__ Wq,
                               const float* __restrict__ Wk,
                               const float* __restrict__ Wv,
                               int xblocks) {
    const int bid = blockIdx.x;
    if (bid < xblocks) {
        // x: one uint4 (8 f16) per thread
        const int j = bid * 256 + threadIdx.x;           // uint4 index
        const float4 f0 = *reinterpret_cast<const float4*>(&x[j * 8]);
        const float4 f1 = *reinterpret_cast<const float4*>(&x[j * 8 + 4]);
        uint4 o;
        o.x = pack_f16(f0.x, f0.y); o.y = pack_f16(f0.z, f0.w);
        o.z = pack_f16(f1.x, f1.y); o.w = pack_f16(f1.z, f1.w);
        reinterpret_cast<uint4*>(g_xh)[j] = o;
    } else {
        // W transpose: one word per thread. i -> (z, kw, n), coalesced in n.
        const int i  = (bid - xblocks) * 256 + threadIdx.x;   // < 98304
        const int n  = i & 255;
        const int kw = (i >> 8) & 127;
        const int z  = i >> 15;
        const float* W = (z == 0) ? Wq : (z == 1) ? Wk : Wv;
        const float a = W[(2 * kw    ) * D_MODEL + n];
        const float b = W[(2 * kw + 1) * D_MODEL + n];
        g_wt[z * 32768 + n * 128 + kw] = pack_f16(a, b);
    }
}

// ---------------------------------------------------------------------------
// Kernel 1: QKV projection, f16 mma, cp.async double-buffer, ldmatrix frags.
// grid = (N/128, 4, 3), block = 256 (8 warps: 4 m x 2 n).
// Dynamic smem: As[2][128][36]w + Ws[2][64][36]w = 55296 B.
// ---------------------------------------------------------------------------
#define AS_WORDS (128 * 36)
#define WS_WORDS (64 * 36)
#define QKV_SMEM ((2 * AS_WORDS + 2 * WS_WORDS) * 4)

__global__ void __launch_bounds__(256, 2)
qkv_mma_kernel(const float* __restrict__ bq, const float* __restrict__ bk,
               const float* __restrict__ bv) {
    extern __shared__ __align__(16) uint32_t dsm[];
    uint32_t* AsW = dsm;                         // [2][128][36]
    uint32_t* WsW = dsm + 2 * AS_WORDS;          // [2][64][36]

    const int z = blockIdx.z;
    const float* bias = (z == 0) ? bq : (z == 1) ? bk : bv;

    const int row0 = blockIdx.x * 128;
    const int n0   = blockIdx.y * 64;
    const int tid  = threadIdx.x;
    const int warp = tid >> 5, lane = tid & 31;
    const int r    = lane >> 2, qq = lane & 3;
    const int wm   = warp >> 1;
    const int wn   = warp & 1;

    const uint32_t as_st = (uint32_t)__cvta_generic_to_shared(AsW);
    const uint32_t ws_st = (uint32_t)__cvta_generic_to_shared(WsW);
    const uint32_t AS_B = AS_WORDS * 4, WS_B = WS_WORDS * 4;

    // cp.async staging: A 1024 uint4 (4/thread), W 512 uint4 (2/thread)
    const uint32_t* xsrc = g_xh + (size_t)row0 * 128;
    const uint32_t* wsrc = g_wt + z * 32768 + n0 * 128;

    auto issue_chunk = [&](int kc) {
        const int buf = kc & 1;
        #pragma unroll
        for (int i = 0; i < 4; i++) {
            const int idx = tid + i * 256;
            const int m = idx >> 3, q = idx & 7;
            cp16(as_st + buf * AS_B + (m * 36 + q * 4) * 4,
                 xsrc + m * 128 + kc * 32 + q * 4);
        }
        #pragma unroll
        for (int i = 0; i < 2; i++) {
            const int idx = tid + i * 256;
            const int n = idx >> 3, q = idx & 7;
            cp16(ws_st + buf * WS_B + (n * 36 + q * 4) * 4,
                 wsrc + n * 128 + kc * 32 + q * 4);
        }
        cp_commit();
    };

    float acc[2][4][4];
    #pragma unroll
    for (int mf = 0; mf < 2; mf++)
        #pragma unroll
        for (int nf = 0; nf < 4; nf++)
            #pragma unroll
            for (int i = 0; i < 4; i++) acc[mf][nf][i] = 0.f;

    // ldmatrix lane bases (rows lane&15, word (lane>>4)*4)
    const uint32_t a_lane = ((wm * 32 + (lane & 15)) * 36 + (lane >> 4) * 4) * 4;
    const uint32_t b_lane = ((wn * 32 + (lane & 15)) * 36 + (lane >> 4) * 4) * 4;

    issue_chunk(0);
    for (int kc = 0; kc < 4; kc++) {
        cp_wait0();
        __syncthreads();
        if (kc < 3) issue_chunk(kc + 1);

        const int buf = kc & 1;
        const uint32_t ab = as_st + buf * AS_B + a_lane;
        const uint32_t bb = ws_st + buf * WS_B + b_lane;
        #pragma unroll
        for (int ks = 0; ks < 4; ks++) {
            uint32_t a[2][4], bf[4][2];
            ldsm_x4(a[0][0], a[0][1], a[0][2], a[0][3], ab + ks * 32);
            ldsm_x4(a[1][0], a[1][1], a[1][2], a[1][3], ab + 16 * 36 * 4 + ks * 32);
            ldsm_x4(bf[0][0], bf[1][0], bf[0][1], bf[1][1], bb + ks * 32);
            ldsm_x4(bf[2][0], bf[3][0], bf[2][1], bf[3][1], bb + 16 * 36 * 4 + ks * 32);
            #pragma unroll
            for (int mf = 0; mf < 2; mf++)
                #pragma unroll
                for (int nf = 0; nf < 4; nf++)
                    mma_f16(acc[mf][nf], a[mf][0], a[mf][1], a[mf][2], a[mf][3],
                            bf[nf][0], bf[nf][1]);
        }
        if (kc < 3) __syncthreads();   // protect buffer reuse for next issue
    }

    const int b  = row0 >> 12;
    const int s0 = row0 & (S_LEN - 1);

    if (z != 2) {
        uint32_t* out = (z == 0) ? g_q : g_k;
        const float scale = (z == 0) ? QK_SCALE : 1.0f;
        const int h  = (n0 >> 5) + wn;
        const int bh = b * NUM_HEADS + h;
        #pragma unroll
        for (int mf = 0; mf < 2; mf++) {
            const int s = s0 + wm * 32 + mf * 16;
            #pragma unroll
            for (int nf = 0; nf < 4; nf++) {
                const float2 bb = *reinterpret_cast<const float2*>(
                    &bias[n0 + wn * 32 + nf * 8 + qq * 2]);
                const float c0 = (acc[mf][nf][0] + bb.x) * scale;
                const float c1 = (acc[mf][nf][1] + bb.y) * scale;
                const float c2 = (acc[mf][nf][2] + bb.x) * scale;
                const float c3 = (acc[mf][nf][3] + bb.y) * scale;
                out[((size_t)bh * S_LEN + s + r    ) * 16 + nf * 4 + qq] = pack_f16(c0, c1);
                out[((size_t)bh * S_LEN + s + r + 8) * 16 + nf * 4 + qq] = pack_f16(c2, c3);
            }
        }
    } else {
        __syncthreads();   // all warps done reading As before reuse as bounce
        __half* Vt = reinterpret_cast<__half*>(dsm);   // [64 n][136 s]
        #pragma unroll
        for (int mf = 0; mf < 2; mf++) {
            const int ml = wm * 32 + mf * 16;
            #pragma unroll
            for (int nf = 0; nf < 4; nf++) {
                const int nc = wn * 32 + nf * 8 + qq * 2;
                const float2 bb = *reinterpret_cast<const float2*>(&bias[n0 + nc]);
                Vt[(nc    ) * 136 + ml + r    ] = __float2half(acc[mf][nf][0] + bb.x);
                Vt[(nc + 1) * 136 + ml + r    ] = __float2half(acc[mf][nf][1] + bb.y);
                Vt[(nc    ) * 136 + ml + r + 8] = __float2half(acc[mf][nf][2] + bb.x);
                Vt[(nc + 1) * 136 + ml + r + 8] = __float2half(acc[mf][nf][3] + bb.y);
            }
        }
        __syncthreads();
        #pragma unroll
        for (int i = 0; i < 4; i++) {
            const int idx = tid + i * 256;
            const int n = idx >> 4, wq = (idx & 15) * 4;
            const uint4 val = *reinterpret_cast<const uint4*>(&Vt[n * 136 + wq * 2]);
            const int col = n0 + n;
            const int bh  = b * NUM_HEADS + (col >> 5);
            const int dh  = col & 31;
            *reinterpret_cast<uint4*>(
                &g_v[((size_t)bh * DIM_HEAD + dh) * (S_LEN / 2) + (s0 >> 1) + wq]) = val;
        }
    }
}

// ---------------------------------------------------------------------------
// Kernel 2: flash attention, f16 mma, f16x2 exp2, l via ones-column mma,
// cp.async 3-stage pipeline (distance 2), one barrier per tile.
// grid = (S/128, H, B), block = 256 (8 warps, 16 q-rows each). BK = 64.
// ---------------------------------------------------------------------------
__global__ void __launch_bounds__(256, 2)
attn_mma_kernel(const float* __restrict__ pad_mask) {
    __shared__ __align__(16) uint32_t Ks[3][64][20];
    __shared__ __align__(16) uint32_t Vs[3][32][36];
    __shared__ __align__(16) float    Ms[3][64];

    const int tid  = threadIdx.x;
    const int warp = tid >> 5;
    const int lane = tid & 31;
    const int r    = lane >> 2;
    const int qq   = lane & 3;

    const int qt = blockIdx.x, h = blockIdx.y, b = blockIdx.z;
    const int bh = b * NUM_HEADS + h;
    const int q0 = qt * 128 + warp * 16;

    const uint32_t ks_st = (uint32_t)__cvta_generic_to_shared(&Ks[0][0][0]);
    const uint32_t vs_st = (uint32_t)__cvta_generic_to_shared(&Vs[0][0][0]);
    const uint32_t ms_st = (uint32_t)__cvta_generic_to_shared(&Ms[0][0]);
    const uint32_t KS_B = 64 * 20 * 4, VS_B = 32 * 36 * 4;
    const uint32_t ONES = 0x3C003C00u;

    const uint32_t ks_lane = (uint32_t)__cvta_generic_to_shared(
        &Ks[0][lane & 7][(lane >> 3) * 4]);
    const uint32_t vs_lane = (uint32_t)__cvta_generic_to_shared(
        &Vs[0][lane & 7][(lane >> 3) * 4]);

    const uint32_t* Kw = g_k + (size_t)bh * S_LEN * 16;
    const uint32_t* Vw = g_v + (size_t)bh * DIM_HEAD * (S_LEN / 2);
    const float* Mp = pad_mask + b * S_LEN;

    auto issue_tile = [&](int t) {
        const int buf = t % 3;
        cp16(ks_st + buf * KS_B + ((tid >> 2) * 20 + (tid & 3) * 4) * 4,
             Kw + t * 1024 + tid * 4);
        cp16(vs_st + buf * VS_B + ((tid >> 3) * 36 + (tid & 7) * 4) * 4,
             Vw + (tid >> 3) * (S_LEN / 2) + t * 32 + (tid & 7) * 4);
        if (tid < 64) cp4(ms_st + buf * 256 + tid * 4, Mp + t * 64 + tid);
        cp_commit();
    };

    // Q fragments (pre-scaled by QK_SCALE)
    uint32_t qa[2][4];
    {
        const uint32_t* Qw = g_q + ((size_t)bh * S_LEN + q0) * 16;
        #pragma unroll
        for (int t = 0; t < 2; t++) {
            qa[t][0] = Qw[(r    ) * 16 + t * 8 + qq    ];
            qa[t][1] = Qw[(r + 8) * 16 + t * 8 + qq    ];
            qa[t][2] = Qw[(r    ) * 16 + t * 8 + qq + 4];
            qa[t][3] = Qw[(r + 8) * 16 + t * 8 + qq + 4];
        }
    }

    float oa[4][4];
    #pragma unroll
    for (int nn = 0; nn < 4; nn++)
        #pragma unroll
        for (int i = 0; i < 4; i++) oa[nn][i] = 0.f;
    float oL[4] = {0.f, 0.f, 0.f, 0.f};

    issue_tile(0);
    issue_tile(1);

    for (int kt = 0; kt < S_LEN / 64; kt++) {
        if (kt < S_LEN / 64 - 1) cp_wait1(); else cp_wait0();
        __syncthreads();
        if (kt + 2 < S_LEN / 64) issue_tile(kt + 2);

        const int p = kt % 3;
        const uint32_t kaddr = ks_lane + (uint32_t)p * KS_B;
        const uint32_t vaddr = vs_lane + (uint32_t)p * VS_B;

        // ---- scores ----
        float sc[8][4];
        #pragma unroll
        for (int j = 0; j < 8; j++) {
            uint32_t b00, b01, b10, b11;
            ldsm_x4(b00, b01, b10, b11, kaddr + j * (8 * 20 * 4));
            sc[j][0] = 0.f; sc[j][1] = 0.f; sc[j][2] = 0.f; sc[j][3] = 0.f;
            mma_f16(sc[j], qa[0][0], qa[0][1], qa[0][2], qa[0][3], b00, b01);
            mma_f16(sc[j], qa[1][0], qa[1][1], qa[1][2], qa[1][3], b10, b11);
        }

        // ---- p = exp2(fma(mask, MASK_LOG2, s)); result IS the PV A-fragment ----
        uint32_t pa[4][4];
        #pragma unroll
        for (int j = 0; j < 8; j++) {
            const float2 mb = *reinterpret_cast<const float2*>(&Ms[p][j * 8 + qq * 2]);
            const uint32_t u01 = pack_f16(fmaf(mb.x, MASK_LOG2, sc[j][0]),
                                          fmaf(mb.y, MASK_LOG2, sc[j][1]));
            const uint32_t u23 = pack_f16(fmaf(mb.x, MASK_LOG2, sc[j][2]),
                                          fmaf(mb.y, MASK_LOG2, sc[j][3]));
            pa[j >> 1][(j & 1) * 2    ] = ex2_f16x2(u01);
            pa[j >> 1][(j & 1) * 2 + 1] = ex2_f16x2(u23);
        }

        // ---- PV (+ ones column for row sums) ----
        #pragma unroll
        for (int nn = 0; nn < 4; nn++) {
            uint32_t vb[4][2];
            ldsm_x4(vb[0][0], vb[0][1], vb[1][0], vb[1][1],
                    vaddr + nn * (8 * 36 * 4));
            ldsm_x4(vb[2][0], vb[2][1], vb[3][0], vb[3][1],
                    vaddr + nn * (8 * 36 * 4) + 64);
            #pragma unroll
            for (int jp = 0; jp < 4; jp++)
                mma_f16(oa[nn], pa[jp][0], pa[jp][1], pa[jp][2], pa[jp][3],
                        vb[jp][0], vb[jp][1]);
        }
        #pragma unroll
        for (int jp = 0; jp < 4; jp++)
            mma_f16(oL, pa[jp][0], pa[jp][1], pa[jp][2], pa[jp][3], ONES, ONES);
    }

    const float i0 = 1.0f / oL[0];
    const float i1 = 1.0f / oL[2];

    float* Op = g_o + ((size_t)bh * S_LEN + q0) * DIM_HEAD;
    #pragma unroll
    for (int nn = 0; nn < 4; nn++) {
        *reinterpret_cast<float2*>(&Op[(r    ) * 32 + nn * 8 + qq * 2]) =
            make_float2(oa[nn][0] * i0, oa[nn][1] * i0);
        *reinterpret_cast<float2*>(&Op[(r + 8) * 32 + nn * 8 + qq * 2]) =
            make_float2(oa[nn][2] * i1, oa[nn][3] * i1);
    }
}

// ---------------------------------------------------------------------------
// Kernel 3: residual + LayerNorm, warp-per-row.
// ---------------------------------------------------------------------------
__global__ void ln_kernel(const float* __restrict__ x,
                          const float* __restrict__ gamma,
                          const float* __restrict__ beta,
                          float* __restrict__ out) {
    const int warp = threadIdx.x >> 5;
    const int lane = threadIdx.x & 31;
    const int row  = blockIdx.x * 8 + warp;
    const int b    = row >> 12;
    const int s    = row & (S_LEN - 1);

    const int d0 = lane * 8;
    const int bh = b * NUM_HEADS + (d0 >> 5);
    const float* Oq = &g_o[((size_t)bh * S_LEN + s) * DIM_HEAD + (d0 & 31)];
    const float* Xq = &x[(size_t)row * D_MODEL + d0];

    float v[8];
    {
        const float4 a0 = *reinterpret_cast<const float4*>(Oq);
        const float4 a1 = *reinterpret_cast<const float4*>(Oq + 4);
        const float4 x0 = *reinterpret_cast<const float4*>(Xq);
        const float4 x1 = *reinterpret_cast<const float4*>(Xq + 4);
        v[0] = a0.x + x0.x; v[1] = a0.y + x0.y; v[2] = a0.z + x0.z; v[3] = a0.w + x0.w;
        v[4] = a1.x + x1.x; v[5] = a1.y + x1.y; v[6] = a1.z + x1.z; v[7] = a1.w + x1.w;
    }

    float sum = 0.f, sq = 0.f;
    #pragma unroll
    for (int i = 0; i < 8; i++) { sum += v[i]; sq += v[i] * v[i]; }
    #pragma unroll
    for (int off = 16; off > 0; off >>= 1) {
        sum += __shfl_xor_sync(FULL_MASK, sum, off);
        sq  += __shfl_xor_sync(FULL_MASK, sq,  off);
    }
    const float mu  = sum * (1.0f / D_MODEL);
    const float var = sq * (1.0f / D_MODEL) - mu * mu;
    const float rs  = rsqrtf(var + LN_EPS);

    const float4 g0 = *reinterpret_cast<const float4*>(&gamma[d0]);
    const float4 g1 = *reinterpret_cast<const float4*>(&gamma[d0 + 4]);
    const float4 b0 = *reinterpret_cast<const float4*>(&beta[d0]);
    const float4 b1 = *reinterpret_cast<const float4*>(&beta[d0 + 4]);

    float4 o0, o1;
    o0.x = g0.x * (v[0] - mu) * rs + b0.x;
    o0.y = g0.y * (v[1] - mu) * rs + b0.y;
    o0.z = g0.z * (v[2] - mu) * rs + b0.z;
    o0.w = g0.w * (v[3] - mu) * rs + b0.w;
    o1.x = g1.x * (v[4] - mu) * rs + b1.x;
    o1.y = g1.y * (v[5] - mu) * rs + b1.y;
    o1.z = g1.z * (v[6] - mu) * rs + b1.z;
    o1.w = g1.w * (v[7] - mu) * rs + b1.w;
    *reinterpret_cast<float4*>(&out[(size_t)row * D_MODEL + d0])     = o0;
    *reinterpret_cast<float4*>(&out[(size_t)row * D_MODEL + d0 + 4]) = o1;
}

// ---------------------------------------------------------------------------
// Launch
// ---------------------------------------------------------------------------
extern "C" void kernel_launch(void* const* d_in, const int* in_sizes, int n_in,
                              void* d_out, int out_size) {
    const float* x     = (const float*)d_in[0];
    const float* pad   = (const float*)d_in[1];
    const float* Wq    = (const float*)d_in[2];
    const float* bq    = (const float*)d_in[3];
    const float* Wk    = (const float*)d_in[4];
    const float* bk    = (const float*)d_in[5];
    const float* Wv    = (const float*)d_in[6];
    const float* bv    = (const float*)d_in[7];
    const float* gamma = (const float*)d_in[8];
    const float* beta  = (const float*)d_in[9];

    const int N = in_sizes[1];            // pad_mask [B,S] -> N = B*S rows
    const int B = N / S_LEN;
    const int xblocks = N * (D_MODEL / 8) / 256;   // one uint4 (8 f16) per thread

    static bool attr_set = false;
    if (!attr_set) {
        cudaFuncSetAttribute(qkv_mma_kernel,
                             cudaFuncAttributeMaxDynamicSharedMemorySize, QKV_SMEM);
        attr_set = true;
    }

    convert_kernel<<<xblocks + 384, 256>>>(x, Wq, Wk, Wv, xblocks);
    qkv_mma_kernel<<<dim3(N / 128, 4, 3), 256, QKV_SMEM>>>(bq, bk, bv);
    attn_mma_kernel<<<dim3(S_LEN / 128, NUM_HEADS, B), 256>>>(pad);
    ln_kernel<<<N / 8, 256>>>(x, gamma, beta, (float*)d_out);
}